// round 6
// baseline (speedup 1.0000x reference)
#include <cuda_runtime.h>
#include <cuda_bf16.h>
#include <mma.h>
#include <math.h>
#include <cstdint>
#include <stdint.h>

using namespace nvcuda;

// Problem constants
#define Lc 15
#define Dc 512
#define Hc 64
#define HDc 8
#define Fc 2048
#define Gc 128
#define Bc 4
#define Nc 256
#define Mc (Bc*Nc)   // 1024 rows
#define SPLITK 4

// Weight split-region bases (elements) inside g_wh/g_wl
#define QKVB 0                 // 15 * 786432  = 11796480
#define OUTB 11796480          // 15 * 262144  = 3932160
#define F1B  15728640          // 15 * 1048576 = 15728640
#define F2B  31457280          // 15 * 1048576 = 15728640
#define WTOT 47185920

// -------- scratch (device globals; no allocation allowed) --------
__device__ float g_h[Mc*Dc];
__device__ float g_qkv[Mc*3*Dc];
__device__ float g_pair[Bc*Nc*Nc];
__device__ float g_split[SPLITK*Mc*Dc];
__device__ __nv_bfloat16 g_xh[Mc*Dc],  g_xl[Mc*Dc];
__device__ __nv_bfloat16 g_ah[Mc*Dc],  g_al[Mc*Dc];
__device__ __nv_bfloat16 g_fh[Mc*Fc],  g_fl[Mc*Fc];
__device__ __nv_bfloat16 g_wh[WTOT],   g_wl[WTOT];

// ---------------- cp.async helpers ----------------
__device__ __forceinline__ void cp16(unsigned d, const void* s) {
    asm volatile("cp.async.cg.shared.global [%0], [%1], 16;\n" :: "r"(d), "l"(s));
}
#define CP_COMMIT() asm volatile("cp.async.commit_group;\n")
#define CP_WAIT(n)  asm volatile("cp.async.wait_group %0;\n" :: "n"(n))

// ---------------- weight split: fp32 -> bf16 hi/lo ----------------
__global__ void wsplit_kernel(const float* __restrict__ src,
                              __nv_bfloat16* __restrict__ dh,
                              __nv_bfloat16* __restrict__ dl, int n4) {
    int i = blockIdx.x*256 + threadIdx.x;
    if (i >= n4) return;
    float4 v = ((const float4*)src)[i];
    __nv_bfloat16 h0 = __float2bfloat16(v.x), h1 = __float2bfloat16(v.y);
    __nv_bfloat16 h2 = __float2bfloat16(v.z), h3 = __float2bfloat16(v.w);
    __nv_bfloat16 l0 = __float2bfloat16(v.x - __bfloat162float(h0));
    __nv_bfloat16 l1 = __float2bfloat16(v.y - __bfloat162float(h1));
    __nv_bfloat16 l2 = __float2bfloat16(v.z - __bfloat162float(h2));
    __nv_bfloat16 l3 = __float2bfloat16(v.w - __bfloat162float(h3));
    ((__nv_bfloat162*)dh)[i*2]   = __halves2bfloat162(h0, h1);
    ((__nv_bfloat162*)dh)[i*2+1] = __halves2bfloat162(h2, h3);
    ((__nv_bfloat162*)dl)[i*2]   = __halves2bfloat162(l0, l1);
    ((__nv_bfloat162*)dl)[i*2+1] = __halves2bfloat162(l2, l3);
}

// ---------------- embedding ----------------
__global__ void emb_kernel(const int* __restrict__ atom_types,
                           const float* __restrict__ atom_emb,
                           float* __restrict__ h) {
    int idx = blockIdx.x * blockDim.x + threadIdx.x;
    if (idx >= Mc*Dc) return;
    int row = idx >> 9;
    int d   = idx & 511;
    h[idx] = atom_emb[atom_types[row]*Dc + d];
}

// ---------------- pair representation ----------------
__global__ void pair_kernel(const float* __restrict__ coords,
                            const int* __restrict__ ptypes,
                            const float* __restrict__ pa,
                            const float* __restrict__ pb,
                            const float* __restrict__ mu,
                            const float* __restrict__ sigma,
                            const float* __restrict__ plw,
                            const float* __restrict__ plb,
                            float* __restrict__ pr) {
    __shared__ float smu[Gc], scoef[Gc];
    int tid = threadIdx.x;
    if (tid < Gc) {
        float sg = sigma[tid];
        scoef[tid] = plw[tid] / (2.0f*sg*sg) / (sg * 2.5066282746310002f);
        smu[tid]   = mu[tid];
    }
    __syncthreads();
    int p = blockIdx.x * blockDim.x + tid;
    int b = p >> 16;
    int rem = p & 65535;
    int i = rem >> 8, j = rem & 255;
    const float* ci = coords + (b*Nc + i)*3;
    const float* cj = coords + (b*Nc + j)*3;
    float dx = ci[0]-cj[0], dy = ci[1]-cj[1], dz = ci[2]-cj[2];
    float d2 = dx*dx + dy*dy + dz*dz;
    float dist = sqrtf(fmaxf(d2, 1e-12f));
    int pt = ptypes[p];
    float da = pa[pt]*dist + pb[pt];
    float s = 0.f;
    #pragma unroll 8
    for (int g = 0; g < Gc; g++) {
        float t = da - smu[g];
        s += __expf(-t*t) * scoef[g];
    }
    pr[p] = s + plb[0];
}

// ---------------- layernorm (emits split bf16) ----------------
__global__ __launch_bounds__(128) void ln_kernel(const float* __restrict__ in,
                                                 const float* __restrict__ g,
                                                 const float* __restrict__ bb,
                                                 __nv_bfloat16* __restrict__ xh,
                                                 __nv_bfloat16* __restrict__ xl) {
    int row = blockIdx.x;
    int tid = threadIdx.x;
    const float* x = in + row*Dc;
    float v[4], s = 0.f, s2 = 0.f;
    #pragma unroll
    for (int j = 0; j < 4; j++) {
        v[j] = x[tid + 128*j];
        s += v[j]; s2 += v[j]*v[j];
    }
    #pragma unroll
    for (int off = 16; off; off >>= 1) {
        s  += __shfl_xor_sync(0xffffffff, s,  off);
        s2 += __shfl_xor_sync(0xffffffff, s2, off);
    }
    __shared__ float rs[4], rs2[4];
    int wid = tid >> 5, lane = tid & 31;
    if (lane == 0) { rs[wid] = s; rs2[wid] = s2; }
    __syncthreads();
    s  = rs[0]+rs[1]+rs[2]+rs[3];
    s2 = rs2[0]+rs2[1]+rs2[2]+rs2[3];
    float mean = s * (1.0f/Dc);
    float var  = s2 * (1.0f/Dc) - mean*mean;
    float rstd = rsqrtf(var + 1e-5f);
    #pragma unroll
    for (int j = 0; j < 4; j++) {
        int d = tid + 128*j;
        float y = (v[j]-mean)*rstd*g[d] + bb[d];
        __nv_bfloat16 hi = __float2bfloat16(y);
        xh[row*Dc + d] = hi;
        xl[row*Dc + d] = __float2bfloat16(y - __bfloat162float(hi));
    }
}

// ---------------- bf16x3 tensor-core GEMM (pre-split operands) ----------------
// D = Ah*Wh^T + Ah*Wl^T + Al*Wh^T  (fp32 accumulate)
// Modes:
//   direct (oh==null && bias==null): raw fp32 frag stores to C (+z*M*N if split-K)
//   staged: +bias [, gelu]; if oh/ol set, write split bf16; else fp32 C (+res)
#define BM 128
#define BN 64
#define BK 32
#define LDA 40
#define LDC 68
#define SM_A_H 0
#define SM_A_L 10240
#define SM_W_H 20480
#define SM_W_L 25600
#define SM_BUF 30720
#define SMEM_DYN 61440
__global__ __launch_bounds__(256, 3) void gemm_tc_kernel(
    const __nv_bfloat16* __restrict__ Ah, const __nv_bfloat16* __restrict__ Al,
    const __nv_bfloat16* __restrict__ Wh, const __nv_bfloat16* __restrict__ Wl,
    const float* __restrict__ bias, const float* __restrict__ res,
    float* __restrict__ C,
    __nv_bfloat16* __restrict__ oh, __nv_bfloat16* __restrict__ ol,
    int M, int N, int K, int act)
{
    extern __shared__ char smem[];
    unsigned sbase = (unsigned)__cvta_generic_to_shared(smem);
    int tid = threadIdx.x;
    int m0 = blockIdx.y*BM, n0 = blockIdx.x*BN;
    int S = gridDim.z;
    int Ks = K / S;
    int kbeg = blockIdx.z * Ks;
    int wid = tid >> 5;
    int wm = (wid >> 1) * 32;
    int wn = (wid & 1) * 32;

    int arow = tid >> 2, acol = (tid & 3) * 8;
    const __nv_bfloat16* pAh0 = Ah + (size_t)(m0+arow)*K + kbeg + acol;
    const __nv_bfloat16* pAh1 = pAh0 + (size_t)64*K;
    const __nv_bfloat16* pAl0 = Al + (size_t)(m0+arow)*K + kbeg + acol;
    const __nv_bfloat16* pAl1 = pAl0 + (size_t)64*K;
    const __nv_bfloat16* pWh  = Wh + (size_t)(n0+arow)*K + kbeg + acol;
    const __nv_bfloat16* pWl  = Wl + (size_t)(n0+arow)*K + kbeg + acol;
    unsigned doffA = (unsigned)(arow*LDA + acol)*2u;

    wmma::fragment<wmma::accumulator, 16, 16, 16, float> acc[2][2];
    #pragma unroll
    for (int i = 0; i < 2; i++)
        #pragma unroll
        for (int j = 0; j < 2; j++)
            wmma::fill_fragment(acc[i][j], 0.0f);

    int nt = Ks / BK;
    // stage tile 0
    {
        unsigned b = sbase;
        cp16(b + SM_A_H + doffA,              pAh0);
        cp16(b + SM_A_H + doffA + 64*LDA*2u,  pAh1);
        cp16(b + SM_A_L + doffA,              pAl0);
        cp16(b + SM_A_L + doffA + 64*LDA*2u,  pAl1);
        cp16(b + SM_W_H + doffA,              pWh);
        cp16(b + SM_W_L + doffA,              pWl);
        CP_COMMIT();
    }
    for (int t = 0; t < nt; t++) {
        int cur = t & 1;
        if (t + 1 < nt) {
            int k0 = (t+1)*BK;
            unsigned b = sbase + (unsigned)(cur^1)*SM_BUF;
            cp16(b + SM_A_H + doffA,             pAh0 + k0);
            cp16(b + SM_A_H + doffA + 64*LDA*2u, pAh1 + k0);
            cp16(b + SM_A_L + doffA,             pAl0 + k0);
            cp16(b + SM_A_L + doffA + 64*LDA*2u, pAl1 + k0);
            cp16(b + SM_W_H + doffA,             pWh + k0);
            cp16(b + SM_W_L + doffA,             pWl + k0);
            CP_COMMIT();
            CP_WAIT(1);
        } else {
            CP_WAIT(0);
        }
        __syncthreads();
        const __nv_bfloat16* sAh = (const __nv_bfloat16*)(smem + cur*SM_BUF + SM_A_H);
        const __nv_bfloat16* sAl = (const __nv_bfloat16*)(smem + cur*SM_BUF + SM_A_L);
        const __nv_bfloat16* sWh = (const __nv_bfloat16*)(smem + cur*SM_BUF + SM_W_H);
        const __nv_bfloat16* sWl = (const __nv_bfloat16*)(smem + cur*SM_BUF + SM_W_L);
        #pragma unroll
        for (int ks = 0; ks < BK; ks += 16) {
            wmma::fragment<wmma::matrix_a, 16, 16, 16, __nv_bfloat16, wmma::row_major> ah[2], al[2];
            #pragma unroll
            for (int i = 0; i < 2; i++) {
                wmma::load_matrix_sync(ah[i], sAh + (wm + i*16)*LDA + ks, LDA);
                wmma::load_matrix_sync(al[i], sAl + (wm + i*16)*LDA + ks, LDA);
            }
            #pragma unroll
            for (int j = 0; j < 2; j++) {
                wmma::fragment<wmma::matrix_b, 16, 16, 16, __nv_bfloat16, wmma::col_major> bh, bl;
                wmma::load_matrix_sync(bh, sWh + (wn + j*16)*LDA + ks, LDA);
                wmma::load_matrix_sync(bl, sWl + (wn + j*16)*LDA + ks, LDA);
                #pragma unroll
                for (int i = 0; i < 2; i++) {
                    wmma::mma_sync(acc[i][j], ah[i], bh, acc[i][j]);
                    wmma::mma_sync(acc[i][j], ah[i], bl, acc[i][j]);
                    wmma::mma_sync(acc[i][j], al[i], bh, acc[i][j]);
                }
            }
        }
        __syncthreads();
    }

    if (oh == nullptr && bias == nullptr) {
        // direct frag stores (QKV raw, split-K partials)
        float* Cp = C + (size_t)blockIdx.z*M*N;
        #pragma unroll
        for (int i = 0; i < 2; i++)
            #pragma unroll
            for (int j = 0; j < 2; j++)
                wmma::store_matrix_sync(Cp + (size_t)(m0+wm+i*16)*N + n0+wn+j*16,
                                        acc[i][j], N, wmma::mem_row_major);
        return;
    }

    // staged epilogue
    float* Ct = (float*)smem;
    #pragma unroll
    for (int i = 0; i < 2; i++)
        #pragma unroll
        for (int j = 0; j < 2; j++)
            wmma::store_matrix_sync(Ct + (wm+i*16)*LDC + wn+j*16,
                                    acc[i][j], LDC, wmma::mem_row_major);
    __syncthreads();

    int col = (tid & 15) * 4;
    int r0  = tid >> 4;
    float4 bv = make_float4(0.f, 0.f, 0.f, 0.f);
    if (bias) bv = *(const float4*)(bias + n0 + col);
    #pragma unroll
    for (int rr = 0; rr < 8; rr++) {
        int row = rr*16 + r0;
        float vr[4];
        *(float4*)vr = *(const float4*)&Ct[row*LDC + col];
        vr[0] += bv.x; vr[1] += bv.y; vr[2] += bv.z; vr[3] += bv.w;
        if (act == 1) {
            #pragma unroll
            for (int j = 0; j < 4; j++)
                vr[j] = 0.5f * vr[j] * (1.0f + erff(vr[j] * 0.7071067811865475f));
        }
        size_t base = (size_t)(m0+row)*N + n0 + col;
        if (oh) {
            __nv_bfloat16 h0 = __float2bfloat16(vr[0]), h1 = __float2bfloat16(vr[1]);
            __nv_bfloat16 h2 = __float2bfloat16(vr[2]), h3 = __float2bfloat16(vr[3]);
            __nv_bfloat16 l0 = __float2bfloat16(vr[0] - __bfloat162float(h0));
            __nv_bfloat16 l1 = __float2bfloat16(vr[1] - __bfloat162float(h1));
            __nv_bfloat16 l2 = __float2bfloat16(vr[2] - __bfloat162float(h2));
            __nv_bfloat16 l3 = __float2bfloat16(vr[3] - __bfloat162float(h3));
            *(__nv_bfloat162*)&oh[base]   = __halves2bfloat162(h0, h1);
            *(__nv_bfloat162*)&oh[base+2] = __halves2bfloat162(h2, h3);
            *(__nv_bfloat162*)&ol[base]   = __halves2bfloat162(l0, l1);
            *(__nv_bfloat162*)&ol[base+2] = __halves2bfloat162(l2, l3);
        } else {
            if (res) {
                float4 r = *(const float4*)(res + base);
                vr[0]+=r.x; vr[1]+=r.y; vr[2]+=r.z; vr[3]+=r.w;
            }
            *(float4*)(C + base) = *(float4*)vr;
        }
    }
}

// ---------------- split-K reduce: h += sum_z partial[z] + bias ----------------
__global__ __launch_bounds__(256) void reduce_splitk(const float* __restrict__ P,
                                                     const float* __restrict__ bias,
                                                     float* __restrict__ h,
                                                     int MN, int N) {
    int i4 = blockIdx.x*256 + threadIdx.x;
    if (i4 >= MN/4) return;
    int n = (i4*4) & (N-1);
    const float4* P4 = (const float4*)P;
    int stride4 = MN/4;
    float4 s0 = P4[i4];
    float4 s1 = P4[i4 + stride4];
    float4 s2 = P4[i4 + 2*stride4];
    float4 s3 = P4[i4 + 3*stride4];
    float4 b  = *(const float4*)(bias + n);
    float4 hv = ((float4*)h)[i4];
    hv.x += s0.x + s1.x + s2.x + s3.x + b.x;
    hv.y += s0.y + s1.y + s2.y + s3.y + b.y;
    hv.z += s0.z + s1.z + s2.z + s3.z + b.z;
    hv.w += s0.w + s1.w + s2.w + s3.w + b.w;
    ((float4*)h)[i4] = hv;
}

// ---------------- fused attention (QKV bias + scores + softmax + PV) ----------------
// qkv: raw bias-free GEMM output. Output: split bf16 (ah/al) for out-proj GEMM.
__global__ __launch_bounds__(256) void attn_kernel(const float* __restrict__ qkv,
                                                   const float* __restrict__ qb,
                                                   const float* __restrict__ pr,
                                                   const float* __restrict__ ppw,
                                                   const float* __restrict__ ppb,
                                                   __nv_bfloat16* __restrict__ oh,
                                                   __nv_bfloat16* __restrict__ ol) {
    int b = blockIdx.x >> 6;
    int h = blockIdx.x & 63;
    __shared__ float Ks[Nc*9];
    __shared__ float Vs[Nc*9];
    int tid = threadIdx.x;
    float4 bq0 = *(const float4*)(qb + h*HDc);
    float4 bq1 = *(const float4*)(qb + h*HDc + 4);
    float4 bk0 = *(const float4*)(qb + Dc + h*HDc);
    float4 bk1 = *(const float4*)(qb + Dc + h*HDc + 4);
    float4 bv0 = *(const float4*)(qb + 2*Dc + h*HDc);
    float4 bv1 = *(const float4*)(qb + 2*Dc + h*HDc + 4);
    {
        int n = tid;
        const float* kp = qkv + (((b*Nc + n)*3 + 1))*Dc + h*HDc;
        const float* vp = kp + Dc;
        float4 k0 = *(const float4*)kp,     k1 = *(const float4*)(kp+4);
        float4 v0 = *(const float4*)vp,     v1 = *(const float4*)(vp+4);
        float* kd = &Ks[n*9];
        kd[0]=k0.x+bk0.x; kd[1]=k0.y+bk0.y; kd[2]=k0.z+bk0.z; kd[3]=k0.w+bk0.w;
        kd[4]=k1.x+bk1.x; kd[5]=k1.y+bk1.y; kd[6]=k1.z+bk1.z; kd[7]=k1.w+bk1.w;
        float* vd = &Vs[n*9];
        vd[0]=v0.x+bv0.x; vd[1]=v0.y+bv0.y; vd[2]=v0.z+bv0.z; vd[3]=v0.w+bv0.w;
        vd[4]=v1.x+bv1.x; vd[5]=v1.y+bv1.y; vd[6]=v1.z+bv1.z; vd[7]=v1.w+bv1.w;
    }
    __syncthreads();
    const float scale = 0.3535533905932738f;
    float pw = ppw[h], pb = ppb[h];
    int warp = tid >> 5, lane = tid & 31;
    #pragma unroll
    for (int r = 0; r < 4; r++) {
        int i = blockIdx.y*32 + warp*4 + r;
        const float* qp = qkv + ((b*Nc + i)*3)*Dc + h*HDc;
        float4 q0 = *(const float4*)qp, q1 = *(const float4*)(qp+4);
        float qr[8];
        qr[0]=q0.x+bq0.x; qr[1]=q0.y+bq0.y; qr[2]=q0.z+bq0.z; qr[3]=q0.w+bq0.w;
        qr[4]=q1.x+bq1.x; qr[5]=q1.y+bq1.y; qr[6]=q1.z+bq1.z; qr[7]=q1.w+bq1.w;
        const float* prow = pr + (b*Nc + i)*Nc;
        float s[8];
        float mx = -1e30f;
        #pragma unroll
        for (int jj = 0; jj < 8; jj++) {
            int j = lane + 32*jj;
            const float* kk = &Ks[j*9];
            float d = qr[0]*kk[0] + qr[1]*kk[1] + qr[2]*kk[2] + qr[3]*kk[3]
                    + qr[4]*kk[4] + qr[5]*kk[5] + qr[6]*kk[6] + qr[7]*kk[7];
            s[jj] = d*scale + prow[j]*pw + pb;
            mx = fmaxf(mx, s[jj]);
        }
        #pragma unroll
        for (int off = 16; off; off >>= 1)
            mx = fmaxf(mx, __shfl_xor_sync(0xffffffff, mx, off));
        float sum = 0.f;
        #pragma unroll
        for (int jj = 0; jj < 8; jj++) { s[jj] = __expf(s[jj]-mx); sum += s[jj]; }
        #pragma unroll
        for (int off = 16; off; off >>= 1)
            sum += __shfl_xor_sync(0xffffffff, sum, off);
        float inv = 1.0f / sum;
        float acc[8] = {};
        #pragma unroll
        for (int jj = 0; jj < 8; jj++) {
            int j = lane + 32*jj;
            float p = s[jj]*inv;
            const float* vv = &Vs[j*9];
            #pragma unroll
            for (int d = 0; d < 8; d++) acc[d] += p*vv[d];
        }
        #pragma unroll
        for (int off = 16; off; off >>= 1) {
            #pragma unroll
            for (int d = 0; d < 8; d++)
                acc[d] += __shfl_xor_sync(0xffffffff, acc[d], off);
        }
        if (lane == 0) {
            size_t base = (size_t)(b*Nc + i)*Dc + h*HDc;
            #pragma unroll
            for (int d = 0; d < 8; d++) {
                __nv_bfloat16 hi = __float2bfloat16(acc[d]);
                oh[base + d] = hi;
                ol[base + d] = __float2bfloat16(acc[d] - __bfloat162float(hi));
            }
        }
    }
}

// ---------------- SE(3) coordinate update ----------------
__global__ __launch_bounds__(128) void coords_kernel(const float* __restrict__ coords,
                                                     const float* __restrict__ pr,
                                                     const float* __restrict__ uw,
                                                     const float* __restrict__ ub,
                                                     const float* __restrict__ ww,
                                                     const float* __restrict__ wb,
                                                     float* __restrict__ out) {
    int gw = blockIdx.x * 4 + (threadIdx.x >> 5);
    int lane = threadIdx.x & 31;
    int b = gw >> 8, i = gw & 255;
    float u0 = uw[0], u1 = ub[0], w0 = ww[0], w1 = wb[0];
    const float* ci = coords + (b*Nc + i)*3;
    float cx = ci[0], cy = ci[1], cz = ci[2];
    float ax = 0.f, ay = 0.f, az = 0.f;
    const float* prow = pr + (b*Nc + i)*Nc;
    #pragma unroll
    for (int jj = 0; jj < 8; jj++) {
        int j = lane + 32*jj;
        const float* cj = coords + (b*Nc + j)*3;
        float c = (fmaxf(prow[j], 0.f)*u0 + u1)*w0 + w1;
        ax += (cx - cj[0])*c;
        ay += (cy - cj[1])*c;
        az += (cz - cj[2])*c;
    }
    #pragma unroll
    for (int off = 16; off; off >>= 1) {
        ax += __shfl_xor_sync(0xffffffff, ax, off);
        ay += __shfl_xor_sync(0xffffffff, ay, off);
        az += __shfl_xor_sync(0xffffffff, az, off);
    }
    if (lane == 0) {
        float invn = 1.0f / (256.0f + 1e-6f);
        float* op = out + (b*Nc + i)*3;
        op[0] = cx + ax*invn;
        op[1] = cy + ay*invn;
        op[2] = cz + az*invn;
    }
}

// ---------------- energy head ----------------
__global__ __launch_bounds__(128) void energy_kernel(const float* __restrict__ h,
                                                     const float* __restrict__ enw,
                                                     const float* __restrict__ enb,
                                                     float* __restrict__ out) {
    int b = blockIdx.x;
    int tid = threadIdx.x;
    const float* row = h + (b*Nc)*Dc;
    float s = 0.f;
    #pragma unroll
    for (int j = 0; j < 4; j++) {
        int d = tid + 128*j;
        s += row[d]*enw[d];
    }
    #pragma unroll
    for (int off = 16; off; off >>= 1)
        s += __shfl_xor_sync(0xffffffff, s, off);
    __shared__ float rs[4];
    int wid = tid >> 5, lane = tid & 31;
    if (lane == 0) rs[wid] = s;
    __syncthreads();
    if (tid == 0)
        out[Bc*Nc*3 + b] = rs[0]+rs[1]+rs[2]+rs[3] + enb[0];
}

// ---------------- host ----------------
extern "C" void kernel_launch(void* const* d_in, const int* in_sizes, int n_in,
                              void* d_out, int out_size) {
    bool has_mask = (n_in >= 31);
    auto IN = [&](int i) -> const void* {
        int k = i;
        if (!has_mask && i > 3) k = i - 1;
        return d_in[k];
    };
    const int*   atom_types = (const int*)  IN(0);
    const float* coords     = (const float*)IN(1);
    const int*   pair_types = (const int*)  IN(2);
    const float* atom_emb   = (const float*)IN(4);
    const float* gmu        = (const float*)IN(5);
    const float* gsigma     = (const float*)IN(6);
    const float* pair_a     = (const float*)IN(7);
    const float* pair_b     = (const float*)IN(8);
    const float* pl_w       = (const float*)IN(9);
    const float* pl_b       = (const float*)IN(10);
    const float* ln1_g      = (const float*)IN(11);
    const float* ln1_b      = (const float*)IN(12);
    const float* qkv_w      = (const float*)IN(13);
    const float* qkv_b      = (const float*)IN(14);
    const float* pp_w       = (const float*)IN(15);
    const float* pp_b       = (const float*)IN(16);
    const float* out_w      = (const float*)IN(17);
    const float* out_b      = (const float*)IN(18);
    const float* ln2_g      = (const float*)IN(19);
    const float* ln2_b      = (const float*)IN(20);
    const float* ffn_w1     = (const float*)IN(21);
    const float* ffn_b1     = (const float*)IN(22);
    const float* ffn_w2     = (const float*)IN(23);
    const float* ffn_b2     = (const float*)IN(24);
    const float* se3_uw     = (const float*)IN(25);
    const float* se3_ub     = (const float*)IN(26);
    const float* se3_ww     = (const float*)IN(27);
    const float* se3_wb     = (const float*)IN(28);
    const float* en_w       = (const float*)IN(29);
    const float* en_b       = (const float*)IN(30);
    float* out = (float*)d_out;

    float *hb, *qkvb, *pairb, *splitb;
    __nv_bfloat16 *xh, *xl, *ah, *al, *fh, *fl, *wh, *wl;
    cudaGetSymbolAddress((void**)&hb,     g_h);
    cudaGetSymbolAddress((void**)&qkvb,   g_qkv);
    cudaGetSymbolAddress((void**)&pairb,  g_pair);
    cudaGetSymbolAddress((void**)&splitb, g_split);
    cudaGetSymbolAddress((void**)&xh, g_xh);
    cudaGetSymbolAddress((void**)&xl, g_xl);
    cudaGetSymbolAddress((void**)&ah, g_ah);
    cudaGetSymbolAddress((void**)&al, g_al);
    cudaGetSymbolAddress((void**)&fh, g_fh);
    cudaGetSymbolAddress((void**)&fl, g_fl);
    cudaGetSymbolAddress((void**)&wh, g_wh);
    cudaGetSymbolAddress((void**)&wl, g_wl);

    cudaFuncSetAttribute(gemm_tc_kernel,
                         cudaFuncAttributeMaxDynamicSharedMemorySize, SMEM_DYN);

    // pre-split all weights into bf16 hi/lo
    wsplit_kernel<<<(11796480/4 + 255)/256, 256>>>(qkv_w,  wh + QKVB, wl + QKVB, 11796480/4);
    wsplit_kernel<<<( 3932160/4 + 255)/256, 256>>>(out_w,  wh + OUTB, wl + OUTB,  3932160/4);
    wsplit_kernel<<<(15728640/4 + 255)/256, 256>>>(ffn_w1, wh + F1B,  wl + F1B,  15728640/4);
    wsplit_kernel<<<(15728640/4 + 255)/256, 256>>>(ffn_w2, wh + F2B,  wl + F2B,  15728640/4);

    emb_kernel<<<(Mc*Dc + 255)/256, 256>>>(atom_types, atom_emb, hb);
    pair_kernel<<<(Bc*Nc*Nc)/256, 256>>>(coords, pair_types, pair_a, pair_b,
                                         gmu, gsigma, pl_w, pl_b, pairb);

    for (int l = 0; l < Lc; l++) {
        const float* l1g = ln1_g + l*Dc;
        const float* l1b = ln1_b + l*Dc;
        const float* qb  = qkv_b + l*3*Dc;
        const float* pwp = pp_w + l*Hc;
        const float* pbp = pp_b + l*Hc;
        const float* ob  = out_b + l*Dc;
        const float* l2g = ln2_g + l*Dc;
        const float* l2b = ln2_b + l*Dc;
        const float* b1  = ffn_b1 + l*Fc;
        const float* b2  = ffn_b2 + l*Dc;
        const __nv_bfloat16* qwh = wh + QKVB + (size_t)l*786432;
        const __nv_bfloat16* qwl = wl + QKVB + (size_t)l*786432;
        const __nv_bfloat16* owh = wh + OUTB + (size_t)l*262144;
        const __nv_bfloat16* owl = wl + OUTB + (size_t)l*262144;
        const __nv_bfloat16* w1h = wh + F1B  + (size_t)l*1048576;
        const __nv_bfloat16* w1l = wl + F1B  + (size_t)l*1048576;
        const __nv_bfloat16* w2h = wh + F2B  + (size_t)l*1048576;
        const __nv_bfloat16* w2l = wl + F2B  + (size_t)l*1048576;

        ln_kernel<<<Mc, 128>>>(hb, l1g, l1b, xh, xl);
        gemm_tc_kernel<<<dim3((3*Dc)/BN, Mc/BM, 1), 256, SMEM_DYN>>>(
            xh, xl, qwh, qwl, nullptr, nullptr, qkvb, nullptr, nullptr,
            Mc, 3*Dc, Dc, 0);
        attn_kernel<<<dim3(Bc*Hc, 8), 256>>>(qkvb, qb, pairb, pwp, pbp, ah, al);
        gemm_tc_kernel<<<dim3(Dc/BN, Mc/BM, SPLITK), 256, SMEM_DYN>>>(
            ah, al, owh, owl, nullptr, nullptr, splitb, nullptr, nullptr,
            Mc, Dc, Dc, 0);
        reduce_splitk<<<(Mc*Dc/4 + 255)/256, 256>>>(splitb, ob, hb, Mc*Dc, Dc);
        ln_kernel<<<Mc, 128>>>(hb, l2g, l2b, xh, xl);
        gemm_tc_kernel<<<dim3(Fc/BN, Mc/BM, 1), 256, SMEM_DYN>>>(
            xh, xl, w1h, w1l, b1, nullptr, nullptr, fh, fl,
            Mc, Fc, Dc, 1);
        gemm_tc_kernel<<<dim3(Dc/BN, Mc/BM, SPLITK), 256, SMEM_DYN>>>(
            fh, fl, w2h, w2l, nullptr, nullptr, splitb, nullptr, nullptr,
            Mc, Dc, Fc, 0);
        reduce_splitk<<<(Mc*Dc/4 + 255)/256, 256>>>(splitb, b2, hb, Mc*Dc, Dc);
    }

    coords_kernel<<<(Bc*Nc)/4, 128>>>(coords, pairb, se3_uw, se3_ub, se3_ww, se3_wb, out);
    energy_kernel<<<Bc, 128>>>(hb, en_w, en_b, out);
    (void)in_sizes; (void)out_size;
}

// round 7
// speedup vs baseline: 1.0369x; 1.0369x over previous
#include <cuda_runtime.h>
#include <cuda_bf16.h>
#include <mma.h>
#include <math.h>
#include <cstdint>
#include <stdint.h>

using namespace nvcuda;

// Problem constants
#define Lc 15
#define Dc 512
#define Hc 64
#define HDc 8
#define Fc 2048
#define Gc 128
#define Bc 4
#define Nc 256
#define Mc (Bc*Nc)   // 1024 rows
#define SPLITK 4

// Weight split-region bases (elements) inside g_wh/g_wl
#define QKVB 0                 // 15 * 786432  = 11796480
#define OUTB 11796480          // 15 * 262144  = 3932160
#define F1B  15728640          // 15 * 1048576 = 15728640
#define F2B  31457280          // 15 * 1048576 = 15728640
#define WTOT 47185920

// -------- scratch (device globals; no allocation allowed) --------
__device__ float g_h[Mc*Dc];
__device__ float g_qkv[Mc*3*Dc];
__device__ float g_pair[Bc*Nc*Nc];
__device__ float g_split[SPLITK*Mc*Dc];
__device__ __nv_bfloat16 g_xh[Mc*Dc],  g_xl[Mc*Dc];
__device__ __nv_bfloat16 g_ah[Mc*Dc],  g_al[Mc*Dc];
__device__ __nv_bfloat16 g_fh[Mc*Fc],  g_fl[Mc*Fc];
__device__ __nv_bfloat16 g_wh[WTOT],   g_wl[WTOT];

// ---------------- cp.async helpers ----------------
__device__ __forceinline__ void cp16(unsigned d, const void* s) {
    asm volatile("cp.async.cg.shared.global [%0], [%1], 16;\n" :: "r"(d), "l"(s));
}
#define CP_COMMIT() asm volatile("cp.async.commit_group;\n")
#define CP_WAIT(n)  asm volatile("cp.async.wait_group %0;\n" :: "n"(n))

// ---------------- weight split: fp32 -> bf16 hi/lo ----------------
__global__ void wsplit_kernel(const float* __restrict__ src,
                              __nv_bfloat16* __restrict__ dh,
                              __nv_bfloat16* __restrict__ dl, int n4) {
    int i = blockIdx.x*256 + threadIdx.x;
    if (i >= n4) return;
    float4 v = ((const float4*)src)[i];
    __nv_bfloat16 h0 = __float2bfloat16(v.x), h1 = __float2bfloat16(v.y);
    __nv_bfloat16 h2 = __float2bfloat16(v.z), h3 = __float2bfloat16(v.w);
    __nv_bfloat16 l0 = __float2bfloat16(v.x - __bfloat162float(h0));
    __nv_bfloat16 l1 = __float2bfloat16(v.y - __bfloat162float(h1));
    __nv_bfloat16 l2 = __float2bfloat16(v.z - __bfloat162float(h2));
    __nv_bfloat16 l3 = __float2bfloat16(v.w - __bfloat162float(h3));
    ((__nv_bfloat162*)dh)[i*2]   = __halves2bfloat162(h0, h1);
    ((__nv_bfloat162*)dh)[i*2+1] = __halves2bfloat162(h2, h3);
    ((__nv_bfloat162*)dl)[i*2]   = __halves2bfloat162(l0, l1);
    ((__nv_bfloat162*)dl)[i*2+1] = __halves2bfloat162(l2, l3);
}

// ---------------- embedding ----------------
__global__ void emb_kernel(const int* __restrict__ atom_types,
                           const float* __restrict__ atom_emb,
                           float* __restrict__ h) {
    int idx = blockIdx.x * blockDim.x + threadIdx.x;
    if (idx >= Mc*Dc) return;
    int row = idx >> 9;
    int d   = idx & 511;
    h[idx] = atom_emb[atom_types[row]*Dc + d];
}

// ---------------- pair representation ----------------
__global__ void pair_kernel(const float* __restrict__ coords,
                            const int* __restrict__ ptypes,
                            const float* __restrict__ pa,
                            const float* __restrict__ pb,
                            const float* __restrict__ mu,
                            const float* __restrict__ sigma,
                            const float* __restrict__ plw,
                            const float* __restrict__ plb,
                            float* __restrict__ pr) {
    __shared__ float smu[Gc], scoef[Gc];
    int tid = threadIdx.x;
    if (tid < Gc) {
        float sg = sigma[tid];
        scoef[tid] = plw[tid] / (2.0f*sg*sg) / (sg * 2.5066282746310002f);
        smu[tid]   = mu[tid];
    }
    __syncthreads();
    int p = blockIdx.x * blockDim.x + tid;
    int b = p >> 16;
    int rem = p & 65535;
    int i = rem >> 8, j = rem & 255;
    const float* ci = coords + (b*Nc + i)*3;
    const float* cj = coords + (b*Nc + j)*3;
    float dx = ci[0]-cj[0], dy = ci[1]-cj[1], dz = ci[2]-cj[2];
    float d2 = dx*dx + dy*dy + dz*dz;
    float dist = sqrtf(fmaxf(d2, 1e-12f));
    int pt = ptypes[p];
    float da = pa[pt]*dist + pb[pt];
    float s = 0.f;
    #pragma unroll 8
    for (int g = 0; g < Gc; g++) {
        float t = da - smu[g];
        s += __expf(-t*t) * scoef[g];
    }
    pr[p] = s + plb[0];
}

// ---------------- layernorm (emits split bf16) ----------------
__global__ __launch_bounds__(128) void ln_kernel(const float* __restrict__ in,
                                                 const float* __restrict__ g,
                                                 const float* __restrict__ bb,
                                                 __nv_bfloat16* __restrict__ xh,
                                                 __nv_bfloat16* __restrict__ xl) {
    int row = blockIdx.x;
    int tid = threadIdx.x;
    const float* x = in + row*Dc;
    float v[4], s = 0.f, s2 = 0.f;
    #pragma unroll
    for (int j = 0; j < 4; j++) {
        v[j] = x[tid + 128*j];
        s += v[j]; s2 += v[j]*v[j];
    }
    #pragma unroll
    for (int off = 16; off; off >>= 1) {
        s  += __shfl_xor_sync(0xffffffff, s,  off);
        s2 += __shfl_xor_sync(0xffffffff, s2, off);
    }
    __shared__ float rs[4], rs2[4];
    int wid = tid >> 5, lane = tid & 31;
    if (lane == 0) { rs[wid] = s; rs2[wid] = s2; }
    __syncthreads();
    s  = rs[0]+rs[1]+rs[2]+rs[3];
    s2 = rs2[0]+rs2[1]+rs2[2]+rs2[3];
    float mean = s * (1.0f/Dc);
    float var  = s2 * (1.0f/Dc) - mean*mean;
    float rstd = rsqrtf(var + 1e-5f);
    #pragma unroll
    for (int j = 0; j < 4; j++) {
        int d = tid + 128*j;
        float y = (v[j]-mean)*rstd*g[d] + bb[d];
        __nv_bfloat16 hi = __float2bfloat16(y);
        xh[row*Dc + d] = hi;
        xl[row*Dc + d] = __float2bfloat16(y - __bfloat162float(hi));
    }
}

// ---------------- bf16x3 tensor-core GEMM (pre-split operands) ----------------
// D = Ah*Wh^T + Ah*Wl^T + Al*Wh^T  (fp32 accumulate)
// Modes:
//   direct (oh==null && bias==null): raw fp32 frag stores to C (+z*M*N if split-K)
//   staged: +bias [, gelu]; if oh/ol set, write split bf16; else fp32 C (+res)
#define BM 128
#define BN 64
#define BK 32
#define LDA 40
#define LDC 68
#define SM_A_H 0
#define SM_A_L 10240
#define SM_W_H 20480
#define SM_W_L 25600
#define SM_BUF 30720
#define SMEM_DYN 61440
__global__ __launch_bounds__(256, 2) void gemm_tc_kernel(
    const __nv_bfloat16* __restrict__ Ah, const __nv_bfloat16* __restrict__ Al,
    const __nv_bfloat16* __restrict__ Wh, const __nv_bfloat16* __restrict__ Wl,
    const float* __restrict__ bias, const float* __restrict__ res,
    float* __restrict__ C,
    __nv_bfloat16* __restrict__ oh, __nv_bfloat16* __restrict__ ol,
    int M, int N, int K, int act)
{
    extern __shared__ char smem[];
    unsigned sbase = (unsigned)__cvta_generic_to_shared(smem);
    int tid = threadIdx.x;
    int m0 = blockIdx.y*BM, n0 = blockIdx.x*BN;
    int S = gridDim.z;
    int Ks = K / S;
    int kbeg = blockIdx.z * Ks;
    int wid = tid >> 5;
    int wm = (wid >> 1) * 32;
    int wn = (wid & 1) * 32;

    int arow = tid >> 2, acol = (tid & 3) * 8;
    const __nv_bfloat16* pAh0 = Ah + (size_t)(m0+arow)*K + kbeg + acol;
    const __nv_bfloat16* pAh1 = pAh0 + (size_t)64*K;
    const __nv_bfloat16* pAl0 = Al + (size_t)(m0+arow)*K + kbeg + acol;
    const __nv_bfloat16* pAl1 = pAl0 + (size_t)64*K;
    const __nv_bfloat16* pWh  = Wh + (size_t)(n0+arow)*K + kbeg + acol;
    const __nv_bfloat16* pWl  = Wl + (size_t)(n0+arow)*K + kbeg + acol;
    unsigned doffA = (unsigned)(arow*LDA + acol)*2u;

    wmma::fragment<wmma::accumulator, 16, 16, 16, float> acc[2][2];
    #pragma unroll
    for (int i = 0; i < 2; i++)
        #pragma unroll
        for (int j = 0; j < 2; j++)
            wmma::fill_fragment(acc[i][j], 0.0f);

    int nt = Ks / BK;
    // stage tile 0
    {
        unsigned b = sbase;
        cp16(b + SM_A_H + doffA,              pAh0);
        cp16(b + SM_A_H + doffA + 64*LDA*2u,  pAh1);
        cp16(b + SM_A_L + doffA,              pAl0);
        cp16(b + SM_A_L + doffA + 64*LDA*2u,  pAl1);
        cp16(b + SM_W_H + doffA,              pWh);
        cp16(b + SM_W_L + doffA,              pWl);
        CP_COMMIT();
    }
    for (int t = 0; t < nt; t++) {
        int cur = t & 1;
        if (t + 1 < nt) {
            int k0 = (t+1)*BK;
            unsigned b = sbase + (unsigned)(cur^1)*SM_BUF;
            cp16(b + SM_A_H + doffA,             pAh0 + k0);
            cp16(b + SM_A_H + doffA + 64*LDA*2u, pAh1 + k0);
            cp16(b + SM_A_L + doffA,             pAl0 + k0);
            cp16(b + SM_A_L + doffA + 64*LDA*2u, pAl1 + k0);
            cp16(b + SM_W_H + doffA,             pWh + k0);
            cp16(b + SM_W_L + doffA,             pWl + k0);
            CP_COMMIT();
            CP_WAIT(1);
        } else {
            CP_WAIT(0);
        }
        __syncthreads();
        const __nv_bfloat16* sAh = (const __nv_bfloat16*)(smem + cur*SM_BUF + SM_A_H);
        const __nv_bfloat16* sAl = (const __nv_bfloat16*)(smem + cur*SM_BUF + SM_A_L);
        const __nv_bfloat16* sWh = (const __nv_bfloat16*)(smem + cur*SM_BUF + SM_W_H);
        const __nv_bfloat16* sWl = (const __nv_bfloat16*)(smem + cur*SM_BUF + SM_W_L);
        #pragma unroll
        for (int ks = 0; ks < BK; ks += 16) {
            wmma::fragment<wmma::matrix_a, 16, 16, 16, __nv_bfloat16, wmma::row_major> ah[2], al[2];
            #pragma unroll
            for (int i = 0; i < 2; i++) {
                wmma::load_matrix_sync(ah[i], sAh + (wm + i*16)*LDA + ks, LDA);
                wmma::load_matrix_sync(al[i], sAl + (wm + i*16)*LDA + ks, LDA);
            }
            #pragma unroll
            for (int j = 0; j < 2; j++) {
                wmma::fragment<wmma::matrix_b, 16, 16, 16, __nv_bfloat16, wmma::col_major> bh, bl;
                wmma::load_matrix_sync(bh, sWh + (wn + j*16)*LDA + ks, LDA);
                wmma::load_matrix_sync(bl, sWl + (wn + j*16)*LDA + ks, LDA);
                #pragma unroll
                for (int i = 0; i < 2; i++) {
                    wmma::mma_sync(acc[i][j], ah[i], bh, acc[i][j]);
                    wmma::mma_sync(acc[i][j], ah[i], bl, acc[i][j]);
                    wmma::mma_sync(acc[i][j], al[i], bh, acc[i][j]);
                }
            }
        }
        __syncthreads();
    }

    if (oh == nullptr && bias == nullptr) {
        // direct frag stores (QKV raw, split-K partials)
        float* Cp = C + (size_t)blockIdx.z*M*N;
        #pragma unroll
        for (int i = 0; i < 2; i++)
            #pragma unroll
            for (int j = 0; j < 2; j++)
                wmma::store_matrix_sync(Cp + (size_t)(m0+wm+i*16)*N + n0+wn+j*16,
                                        acc[i][j], N, wmma::mem_row_major);
        return;
    }

    // staged epilogue
    float* Ct = (float*)smem;
    #pragma unroll
    for (int i = 0; i < 2; i++)
        #pragma unroll
        for (int j = 0; j < 2; j++)
            wmma::store_matrix_sync(Ct + (wm+i*16)*LDC + wn+j*16,
                                    acc[i][j], LDC, wmma::mem_row_major);
    __syncthreads();

    int col = (tid & 15) * 4;
    int r0  = tid >> 4;
    float4 bv = make_float4(0.f, 0.f, 0.f, 0.f);
    if (bias) bv = *(const float4*)(bias + n0 + col);
    #pragma unroll
    for (int rr = 0; rr < 8; rr++) {
        int row = rr*16 + r0;
        float vr[4];
        *(float4*)vr = *(const float4*)&Ct[row*LDC + col];
        vr[0] += bv.x; vr[1] += bv.y; vr[2] += bv.z; vr[3] += bv.w;
        if (act == 1) {
            #pragma unroll
            for (int j = 0; j < 4; j++)
                vr[j] = 0.5f * vr[j] * (1.0f + erff(vr[j] * 0.7071067811865475f));
        }
        size_t base = (size_t)(m0+row)*N + n0 + col;
        if (oh) {
            __nv_bfloat16 h0 = __float2bfloat16(vr[0]), h1 = __float2bfloat16(vr[1]);
            __nv_bfloat16 h2 = __float2bfloat16(vr[2]), h3 = __float2bfloat16(vr[3]);
            __nv_bfloat16 l0 = __float2bfloat16(vr[0] - __bfloat162float(h0));
            __nv_bfloat16 l1 = __float2bfloat16(vr[1] - __bfloat162float(h1));
            __nv_bfloat16 l2 = __float2bfloat16(vr[2] - __bfloat162float(h2));
            __nv_bfloat16 l3 = __float2bfloat16(vr[3] - __bfloat162float(h3));
            *(__nv_bfloat162*)&oh[base]   = __halves2bfloat162(h0, h1);
            *(__nv_bfloat162*)&oh[base+2] = __halves2bfloat162(h2, h3);
            *(__nv_bfloat162*)&ol[base]   = __halves2bfloat162(l0, l1);
            *(__nv_bfloat162*)&ol[base+2] = __halves2bfloat162(l2, l3);
        } else {
            if (res) {
                float4 r = *(const float4*)(res + base);
                vr[0]+=r.x; vr[1]+=r.y; vr[2]+=r.z; vr[3]+=r.w;
            }
            *(float4*)(C + base) = *(float4*)vr;
        }
    }
}

// ---------------- split-K reduce: h += sum_z partial[z] + bias ----------------
__global__ __launch_bounds__(256) void reduce_splitk(const float* __restrict__ P,
                                                     const float* __restrict__ bias,
                                                     float* __restrict__ h,
                                                     int MN, int N) {
    int i4 = blockIdx.x*256 + threadIdx.x;
    if (i4 >= MN/4) return;
    int n = (i4*4) & (N-1);
    const float4* P4 = (const float4*)P;
    int stride4 = MN/4;
    float4 s0 = P4[i4];
    float4 s1 = P4[i4 + stride4];
    float4 s2 = P4[i4 + 2*stride4];
    float4 s3 = P4[i4 + 3*stride4];
    float4 b  = *(const float4*)(bias + n);
    float4 hv = ((float4*)h)[i4];
    hv.x += s0.x + s1.x + s2.x + s3.x + b.x;
    hv.y += s0.y + s1.y + s2.y + s3.y + b.y;
    hv.z += s0.z + s1.z + s2.z + s3.z + b.z;
    hv.w += s0.w + s1.w + s2.w + s3.w + b.w;
    ((float4*)h)[i4] = hv;
}

// ---------------- fused attention (QKV bias + scores + softmax + PV) ----------------
// qkv: raw bias-free GEMM output. Output: split bf16 (ah/al) for out-proj GEMM.
__global__ __launch_bounds__(256) void attn_kernel(const float* __restrict__ qkv,
                                                   const float* __restrict__ qb,
                                                   const float* __restrict__ pr,
                                                   const float* __restrict__ ppw,
                                                   const float* __restrict__ ppb,
                                                   __nv_bfloat16* __restrict__ oh,
                                                   __nv_bfloat16* __restrict__ ol) {
    int b = blockIdx.x >> 6;
    int h = blockIdx.x & 63;
    __shared__ float Ks[Nc*9];
    __shared__ float Vs[Nc*9];
    int tid = threadIdx.x;
    float4 bq0 = *(const float4*)(qb + h*HDc);
    float4 bq1 = *(const float4*)(qb + h*HDc + 4);
    float4 bk0 = *(const float4*)(qb + Dc + h*HDc);
    float4 bk1 = *(const float4*)(qb + Dc + h*HDc + 4);
    float4 bv0 = *(const float4*)(qb + 2*Dc + h*HDc);
    float4 bv1 = *(const float4*)(qb + 2*Dc + h*HDc + 4);
    {
        int n = tid;
        const float* kp = qkv + (((b*Nc + n)*3 + 1))*Dc + h*HDc;
        const float* vp = kp + Dc;
        float4 k0 = *(const float4*)kp,     k1 = *(const float4*)(kp+4);
        float4 v0 = *(const float4*)vp,     v1 = *(const float4*)(vp+4);
        float* kd = &Ks[n*9];
        kd[0]=k0.x+bk0.x; kd[1]=k0.y+bk0.y; kd[2]=k0.z+bk0.z; kd[3]=k0.w+bk0.w;
        kd[4]=k1.x+bk1.x; kd[5]=k1.y+bk1.y; kd[6]=k1.z+bk1.z; kd[7]=k1.w+bk1.w;
        float* vd = &Vs[n*9];
        vd[0]=v0.x+bv0.x; vd[1]=v0.y+bv0.y; vd[2]=v0.z+bv0.z; vd[3]=v0.w+bv0.w;
        vd[4]=v1.x+bv1.x; vd[5]=v1.y+bv1.y; vd[6]=v1.z+bv1.z; vd[7]=v1.w+bv1.w;
    }
    __syncthreads();
    const float scale = 0.3535533905932738f;
    float pw = ppw[h], pb = ppb[h];
    int warp = tid >> 5, lane = tid & 31;
    #pragma unroll
    for (int r = 0; r < 4; r++) {
        int i = blockIdx.y*32 + warp*4 + r;
        const float* qp = qkv + ((b*Nc + i)*3)*Dc + h*HDc;
        float4 q0 = *(const float4*)qp, q1 = *(const float4*)(qp+4);
        float qr[8];
        qr[0]=q0.x+bq0.x; qr[1]=q0.y+bq0.y; qr[2]=q0.z+bq0.z; qr[3]=q0.w+bq0.w;
        qr[4]=q1.x+bq1.x; qr[5]=q1.y+bq1.y; qr[6]=q1.z+bq1.z; qr[7]=q1.w+bq1.w;
        const float* prow = pr + (b*Nc + i)*Nc;
        float s[8];
        float mx = -1e30f;
        #pragma unroll
        for (int jj = 0; jj < 8; jj++) {
            int j = lane + 32*jj;
            const float* kk = &Ks[j*9];
            float d = qr[0]*kk[0] + qr[1]*kk[1] + qr[2]*kk[2] + qr[3]*kk[3]
                    + qr[4]*kk[4] + qr[5]*kk[5] + qr[6]*kk[6] + qr[7]*kk[7];
            s[jj] = d*scale + prow[j]*pw + pb;
            mx = fmaxf(mx, s[jj]);
        }
        #pragma unroll
        for (int off = 16; off; off >>= 1)
            mx = fmaxf(mx, __shfl_xor_sync(0xffffffff, mx, off));
        float sum = 0.f;
        #pragma unroll
        for (int jj = 0; jj < 8; jj++) { s[jj] = __expf(s[jj]-mx); sum += s[jj]; }
        #pragma unroll
        for (int off = 16; off; off >>= 1)
            sum += __shfl_xor_sync(0xffffffff, sum, off);
        float inv = 1.0f / sum;
        float acc[8] = {};
        #pragma unroll
        for (int jj = 0; jj < 8; jj++) {
            int j = lane + 32*jj;
            float p = s[jj]*inv;
            const float* vv = &Vs[j*9];
            #pragma unroll
            for (int d = 0; d < 8; d++) acc[d] += p*vv[d];
        }
        #pragma unroll
        for (int off = 16; off; off >>= 1) {
            #pragma unroll
            for (int d = 0; d < 8; d++)
                acc[d] += __shfl_xor_sync(0xffffffff, acc[d], off);
        }
        if (lane == 0) {
            size_t base = (size_t)(b*Nc + i)*Dc + h*HDc;
            #pragma unroll
            for (int d = 0; d < 8; d++) {
                __nv_bfloat16 hi = __float2bfloat16(acc[d]);
                oh[base + d] = hi;
                ol[base + d] = __float2bfloat16(acc[d] - __bfloat162float(hi));
            }
        }
    }
}

// ---------------- SE(3) coordinate update ----------------
__global__ __launch_bounds__(128) void coords_kernel(const float* __restrict__ coords,
                                                     const float* __restrict__ pr,
                                                     const float* __restrict__ uw,
                                                     const float* __restrict__ ub,
                                                     const float* __restrict__ ww,
                                                     const float* __restrict__ wb,
                                                     float* __restrict__ out) {
    int gw = blockIdx.x * 4 + (threadIdx.x >> 5);
    int lane = threadIdx.x & 31;
    int b = gw >> 8, i = gw & 255;
    float u0 = uw[0], u1 = ub[0], w0 = ww[0], w1 = wb[0];
    const float* ci = coords + (b*Nc + i)*3;
    float cx = ci[0], cy = ci[1], cz = ci[2];
    float ax = 0.f, ay = 0.f, az = 0.f;
    const float* prow = pr + (b*Nc + i)*Nc;
    #pragma unroll
    for (int jj = 0; jj < 8; jj++) {
        int j = lane + 32*jj;
        const float* cj = coords + (b*Nc + j)*3;
        float c = (fmaxf(prow[j], 0.f)*u0 + u1)*w0 + w1;
        ax += (cx - cj[0])*c;
        ay += (cy - cj[1])*c;
        az += (cz - cj[2])*c;
    }
    #pragma unroll
    for (int off = 16; off; off >>= 1) {
        ax += __shfl_xor_sync(0xffffffff, ax, off);
        ay += __shfl_xor_sync(0xffffffff, ay, off);
        az += __shfl_xor_sync(0xffffffff, az, off);
    }
    if (lane == 0) {
        float invn = 1.0f / (256.0f + 1e-6f);
        float* op = out + (b*Nc + i)*3;
        op[0] = cx + ax*invn;
        op[1] = cy + ay*invn;
        op[2] = cz + az*invn;
    }
}

// ---------------- energy head ----------------
__global__ __launch_bounds__(128) void energy_kernel(const float* __restrict__ h,
                                                     const float* __restrict__ enw,
                                                     const float* __restrict__ enb,
                                                     float* __restrict__ out) {
    int b = blockIdx.x;
    int tid = threadIdx.x;
    const float* row = h + (b*Nc)*Dc;
    float s = 0.f;
    #pragma unroll
    for (int j = 0; j < 4; j++) {
        int d = tid + 128*j;
        s += row[d]*enw[d];
    }
    #pragma unroll
    for (int off = 16; off; off >>= 1)
        s += __shfl_xor_sync(0xffffffff, s, off);
    __shared__ float rs[4];
    int wid = tid >> 5, lane = tid & 31;
    if (lane == 0) rs[wid] = s;
    __syncthreads();
    if (tid == 0)
        out[Bc*Nc*3 + b] = rs[0]+rs[1]+rs[2]+rs[3] + enb[0];
}

// ---------------- host ----------------
extern "C" void kernel_launch(void* const* d_in, const int* in_sizes, int n_in,
                              void* d_out, int out_size) {
    bool has_mask = (n_in >= 31);
    auto IN = [&](int i) -> const void* {
        int k = i;
        if (!has_mask && i > 3) k = i - 1;
        return d_in[k];
    };
    const int*   atom_types = (const int*)  IN(0);
    const float* coords     = (const float*)IN(1);
    const int*   pair_types = (const int*)  IN(2);
    const float* atom_emb   = (const float*)IN(4);
    const float* gmu        = (const float*)IN(5);
    const float* gsigma     = (const float*)IN(6);
    const float* pair_a     = (const float*)IN(7);
    const float* pair_b     = (const float*)IN(8);
    const float* pl_w       = (const float*)IN(9);
    const float* pl_b       = (const float*)IN(10);
    const float* ln1_g      = (const float*)IN(11);
    const float* ln1_b      = (const float*)IN(12);
    const float* qkv_w      = (const float*)IN(13);
    const float* qkv_b      = (const float*)IN(14);
    const float* pp_w       = (const float*)IN(15);
    const float* pp_b       = (const float*)IN(16);
    const float* out_w      = (const float*)IN(17);
    const float* out_b      = (const float*)IN(18);
    const float* ln2_g      = (const float*)IN(19);
    const float* ln2_b      = (const float*)IN(20);
    const float* ffn_w1     = (const float*)IN(21);
    const float* ffn_b1     = (const float*)IN(22);
    const float* ffn_w2     = (const float*)IN(23);
    const float* ffn_b2     = (const float*)IN(24);
    const float* se3_uw     = (const float*)IN(25);
    const float* se3_ub     = (const float*)IN(26);
    const float* se3_ww     = (const float*)IN(27);
    const float* se3_wb     = (const float*)IN(28);
    const float* en_w       = (const float*)IN(29);
    const float* en_b       = (const float*)IN(30);
    float* out = (float*)d_out;

    float *hb, *qkvb, *pairb, *splitb;
    __nv_bfloat16 *xh, *xl, *ah, *al, *fh, *fl, *wh, *wl;
    cudaGetSymbolAddress((void**)&hb,     g_h);
    cudaGetSymbolAddress((void**)&qkvb,   g_qkv);
    cudaGetSymbolAddress((void**)&pairb,  g_pair);
    cudaGetSymbolAddress((void**)&splitb, g_split);
    cudaGetSymbolAddress((void**)&xh, g_xh);
    cudaGetSymbolAddress((void**)&xl, g_xl);
    cudaGetSymbolAddress((void**)&ah, g_ah);
    cudaGetSymbolAddress((void**)&al, g_al);
    cudaGetSymbolAddress((void**)&fh, g_fh);
    cudaGetSymbolAddress((void**)&fl, g_fl);
    cudaGetSymbolAddress((void**)&wh, g_wh);
    cudaGetSymbolAddress((void**)&wl, g_wl);

    cudaFuncSetAttribute(gemm_tc_kernel,
                         cudaFuncAttributeMaxDynamicSharedMemorySize, SMEM_DYN);

    // pre-split all weights into bf16 hi/lo
    wsplit_kernel<<<(11796480/4 + 255)/256, 256>>>(qkv_w,  wh + QKVB, wl + QKVB, 11796480/4);
    wsplit_kernel<<<( 3932160/4 + 255)/256, 256>>>(out_w,  wh + OUTB, wl + OUTB,  3932160/4);
    wsplit_kernel<<<(15728640/4 + 255)/256, 256>>>(ffn_w1, wh + F1B,  wl + F1B,  15728640/4);
    wsplit_kernel<<<(15728640/4 + 255)/256, 256>>>(ffn_w2, wh + F2B,  wl + F2B,  15728640/4);

    emb_kernel<<<(Mc*Dc + 255)/256, 256>>>(atom_types, atom_emb, hb);
    pair_kernel<<<(Bc*Nc*Nc)/256, 256>>>(coords, pair_types, pair_a, pair_b,
                                         gmu, gsigma, pl_w, pl_b, pairb);

    for (int l = 0; l < Lc; l++) {
        const float* l1g = ln1_g + l*Dc;
        const float* l1b = ln1_b + l*Dc;
        const float* qb  = qkv_b + l*3*Dc;
        const float* pwp = pp_w + l*Hc;
        const float* pbp = pp_b + l*Hc;
        const float* ob  = out_b + l*Dc;
        const float* l2g = ln2_g + l*Dc;
        const float* l2b = ln2_b + l*Dc;
        const float* b1  = ffn_b1 + l*Fc;
        const float* b2  = ffn_b2 + l*Dc;
        const __nv_bfloat16* qwh = wh + QKVB + (size_t)l*786432;
        const __nv_bfloat16* qwl = wl + QKVB + (size_t)l*786432;
        const __nv_bfloat16* owh = wh + OUTB + (size_t)l*262144;
        const __nv_bfloat16* owl = wl + OUTB + (size_t)l*262144;
        const __nv_bfloat16* w1h = wh + F1B  + (size_t)l*1048576;
        const __nv_bfloat16* w1l = wl + F1B  + (size_t)l*1048576;
        const __nv_bfloat16* w2h = wh + F2B  + (size_t)l*1048576;
        const __nv_bfloat16* w2l = wl + F2B  + (size_t)l*1048576;

        ln_kernel<<<Mc, 128>>>(hb, l1g, l1b, xh, xl);
        gemm_tc_kernel<<<dim3((3*Dc)/BN, Mc/BM, 1), 256, SMEM_DYN>>>(
            xh, xl, qwh, qwl, nullptr, nullptr, qkvb, nullptr, nullptr,
            Mc, 3*Dc, Dc, 0);
        attn_kernel<<<dim3(Bc*Hc, 8), 256>>>(qkvb, qb, pairb, pwp, pbp, ah, al);
        gemm_tc_kernel<<<dim3(Dc/BN, Mc/BM, SPLITK), 256, SMEM_DYN>>>(
            ah, al, owh, owl, nullptr, nullptr, splitb, nullptr, nullptr,
            Mc, Dc, Dc, 0);
        reduce_splitk<<<(Mc*Dc/4 + 255)/256, 256>>>(splitb, ob, hb, Mc*Dc, Dc);
        ln_kernel<<<Mc, 128>>>(hb, l2g, l2b, xh, xl);
        gemm_tc_kernel<<<dim3(Fc/BN, Mc/BM, 1), 256, SMEM_DYN>>>(
            xh, xl, w1h, w1l, b1, nullptr, nullptr, fh, fl,
            Mc, Fc, Dc, 1);
        gemm_tc_kernel<<<dim3(Dc/BN, Mc/BM, SPLITK), 256, SMEM_DYN>>>(
            fh, fl, w2h, w2l, nullptr, nullptr, splitb, nullptr, nullptr,
            Mc, Dc, Fc, 0);
        reduce_splitk<<<(Mc*Dc/4 + 255)/256, 256>>>(splitb, b2, hb, Mc*Dc, Dc);
    }

    coords_kernel<<<(Bc*Nc)/4, 128>>>(coords, pairb, se3_uw, se3_ub, se3_ww, se3_wb, out);
    energy_kernel<<<Bc, 128>>>(hb, en_w, en_b, out);
    (void)in_sizes; (void)out_size;
}

// round 9
// speedup vs baseline: 1.2108x; 1.1677x over previous
#include <cuda_runtime.h>
#include <cuda_bf16.h>
#include <mma.h>
#include <math.h>
#include <cstdint>
#include <stdint.h>

using namespace nvcuda;

// Problem constants
#define Lc 15
#define Dc 512
#define Hc 64
#define HDc 8
#define Fc 2048
#define Gc 128
#define Bc 4
#define Nc 256
#define Mc (Bc*Nc)   // 1024 rows
#define SPLITK 4
#define TABN 8192

// -------- scratch (device globals; no allocation allowed) --------
__device__ float g_h[Mc*Dc];
__device__ float g_x[Mc*Dc];
__device__ float g_qkv[Mc*3*Dc];
__device__ float g_attn[Mc*Dc];
__device__ float g_ffn[Mc*Fc];
__device__ float g_pair[Bc*Nc*Nc];
__device__ float g_split[SPLITK*Mc*Dc];
__device__ float g_tab[TABN+1];

// ---------------- gaussian table build: f(da) = sum_g coef_g exp(-(da-mu_g)^2) + plb ----------------
__global__ void tab_kernel(const float* __restrict__ mu,
                           const float* __restrict__ sigma,
                           const float* __restrict__ plw,
                           const float* __restrict__ plb) {
    int i = blockIdx.x*256 + threadIdx.x;
    if (i > TABN) return;
    float da = -8.0f + (float)i * (1.0f/512.0f);
    float s = 0.f;
    #pragma unroll 8
    for (int g = 0; g < Gc; g++) {
        float sg = sigma[g];
        float coef = plw[g] / (2.0f*sg*sg) / (sg * 2.5066282746310002f);
        float t = da - mu[g];
        s += __expf(-t*t) * coef;
    }
    g_tab[i] = s + plb[0];
}

// ---------------- pair representation via table lookup ----------------
__global__ void pair_kernel(const float* __restrict__ coords,
                            const int* __restrict__ ptypes,
                            const float* __restrict__ pa,
                            const float* __restrict__ pb,
                            float* __restrict__ pr) {
    int p = blockIdx.x * blockDim.x + threadIdx.x;
    int b = p >> 16;
    int rem = p & 65535;
    int i = rem >> 8, j = rem & 255;
    const float* ci = coords + (b*Nc + i)*3;
    const float* cj = coords + (b*Nc + j)*3;
    float dx = ci[0]-cj[0], dy = ci[1]-cj[1], dz = ci[2]-cj[2];
    float d2 = dx*dx + dy*dy + dz*dz;
    float dist = sqrtf(fmaxf(d2, 1e-12f));
    int pt = ptypes[p];
    float da = pa[pt]*dist + pb[pt];
    float t = (da + 8.0f) * 512.0f;
    t = fminf(fmaxf(t, 0.0f), (float)(TABN - 1));
    int idx = (int)t;
    float fr = t - (float)idx;
    float f0 = g_tab[idx], f1 = g_tab[idx+1];
    pr[p] = f0 + fr*(f1 - f0);
}

// ---------------- embedding ----------------
__global__ void emb_kernel(const int* __restrict__ atom_types,
                           const float* __restrict__ atom_emb,
                           float* __restrict__ h) {
    int idx = blockIdx.x * blockDim.x + threadIdx.x;
    if (idx >= Mc*Dc) return;
    int row = idx >> 9;
    int d   = idx & 511;
    h[idx] = atom_emb[atom_types[row]*Dc + d];
}

// ---------------- layernorm ----------------
__global__ __launch_bounds__(128) void ln_kernel(const float* __restrict__ in,
                                                 const float* __restrict__ g,
                                                 const float* __restrict__ bb,
                                                 float* __restrict__ out) {
    int row = blockIdx.x;
    int tid = threadIdx.x;
    const float* x = in + row*Dc;
    float v[4], s = 0.f, s2 = 0.f;
    #pragma unroll
    for (int j = 0; j < 4; j++) {
        v[j] = x[tid + 128*j];
        s += v[j]; s2 += v[j]*v[j];
    }
    #pragma unroll
    for (int off = 16; off; off >>= 1) {
        s  += __shfl_xor_sync(0xffffffff, s,  off);
        s2 += __shfl_xor_sync(0xffffffff, s2, off);
    }
    __shared__ float rs[4], rs2[4];
    int wid = tid >> 5, lane = tid & 31;
    if (lane == 0) { rs[wid] = s; rs2[wid] = s2; }
    __syncthreads();
    s  = rs[0]+rs[1]+rs[2]+rs[3];
    s2 = rs2[0]+rs2[1]+rs2[2]+rs2[3];
    float mean = s * (1.0f/Dc);
    float var  = s2 * (1.0f/Dc) - mean*mean;
    float rstd = rsqrtf(var + 1e-5f);
    #pragma unroll
    for (int j = 0; j < 4; j++) {
        int d = tid + 128*j;
        out[row*Dc + d] = (v[j]-mean)*rstd*g[d] + bb[d];
    }
}

// ---------------- fused split-K reduce + layernorm ----------------
// h[row] += sum_z P[z][row] + bias; then xout[row] = LN(h[row]; g, bb)
__global__ __launch_bounds__(128) void reduce_ln_kernel(
    const float* __restrict__ P, const float* __restrict__ bias,
    float* __restrict__ h, const float* __restrict__ g,
    const float* __restrict__ bb, float* __restrict__ xout) {
    int row = blockIdx.x;
    int tid = threadIdx.x;
    const int MN = Mc*Dc;
    float v[4], s = 0.f, s2 = 0.f;
    #pragma unroll
    for (int j = 0; j < 4; j++) {
        int d = tid + 128*j;
        int idx = row*Dc + d;
        float val = h[idx] + bias[d]
                  + P[idx] + P[idx + MN] + P[idx + 2*MN] + P[idx + 3*MN];
        h[idx] = val;
        v[j] = val; s += val; s2 += val*val;
    }
    #pragma unroll
    for (int off = 16; off; off >>= 1) {
        s  += __shfl_xor_sync(0xffffffff, s,  off);
        s2 += __shfl_xor_sync(0xffffffff, s2, off);
    }
    __shared__ float rs[4], rs2[4];
    int wid = tid >> 5, lane = tid & 31;
    if (lane == 0) { rs[wid] = s; rs2[wid] = s2; }
    __syncthreads();
    s  = rs[0]+rs[1]+rs[2]+rs[3];
    s2 = rs2[0]+rs2[1]+rs2[2]+rs2[3];
    float mean = s * (1.0f/Dc);
    float var  = s2 * (1.0f/Dc) - mean*mean;
    float rstd = rsqrtf(var + 1e-5f);
    #pragma unroll
    for (int j = 0; j < 4; j++) {
        int d = tid + 128*j;
        xout[row*Dc + d] = (v[j]-mean)*rstd*g[d] + bb[d];
    }
}

// ---------------- plain split-K reduce (final layer) ----------------
__global__ __launch_bounds__(256) void reduce_splitk(const float* __restrict__ P,
                                                     const float* __restrict__ bias,
                                                     float* __restrict__ h,
                                                     int MN, int N) {
    int i4 = blockIdx.x*256 + threadIdx.x;
    if (i4 >= MN/4) return;
    int n = (i4*4) & (N-1);
    const float4* P4 = (const float4*)P;
    int stride4 = MN/4;
    float4 s0 = P4[i4];
    float4 s1 = P4[i4 + stride4];
    float4 s2 = P4[i4 + 2*stride4];
    float4 s3 = P4[i4 + 3*stride4];
    float4 b  = *(const float4*)(bias + n);
    float4 hv = ((float4*)h)[i4];
    hv.x += s0.x + s1.x + s2.x + s3.x + b.x;
    hv.y += s0.y + s1.y + s2.y + s3.y + b.y;
    hv.z += s0.z + s1.z + s2.z + s3.z + b.z;
    hv.w += s0.w + s1.w + s2.w + s3.w + b.w;
    ((float4*)h)[i4] = hv;
}

// ---------------- bf16x3 tensor-core GEMM (round-4 verbatim) ----------------
#define BM 128
#define BN 64
#define BKT 32
#define LDA 40
#define LDC 68
__global__ __launch_bounds__(256, 2) void gemm_bf16x3_kernel(
    const float* __restrict__ A, const float* __restrict__ W,
    const float* __restrict__ bias, const float* __restrict__ res,
    float* __restrict__ C, int M, int N, int K, int act)
{
    __shared__ __align__(16) char smem_raw[BM*LDC*4];
    __nv_bfloat16* Ah = (__nv_bfloat16*)smem_raw;
    __nv_bfloat16* Al = Ah + BM*LDA;
    __nv_bfloat16* Wh = Al + BM*LDA;
    __nv_bfloat16* Wl = Wh + BN*LDA;
    float* Ct = (float*)smem_raw;

    int tid = threadIdx.x;
    int m0 = blockIdx.y*BM, n0 = blockIdx.x*BN;
    int S = gridDim.z;
    int Ks = K / S;
    int kbeg = blockIdx.z * Ks;

    int wid = tid >> 5;
    int wm = (wid >> 1) * 32;
    int wn = (wid & 1) * 32;

    wmma::fragment<wmma::accumulator, 16, 16, 16, float> acc[2][2];
    #pragma unroll
    for (int i = 0; i < 2; i++)
        #pragma unroll
        for (int j = 0; j < 2; j++)
            wmma::fill_fragment(acc[i][j], 0.0f);

    float4 pa[4], pw[2];
    #pragma unroll
    for (int i = 0; i < 4; i++) {
        int idx = tid + i*256, row = idx >> 3, c = (idx & 7)*4;
        pa[i] = *(const float4*)(A + (size_t)(m0+row)*K + kbeg + c);
    }
    #pragma unroll
    for (int i = 0; i < 2; i++) {
        int idx = tid + i*256, row = idx >> 3, c = (idx & 7)*4;
        pw[i] = *(const float4*)(W + (size_t)(n0+row)*K + kbeg + c);
    }

    for (int k0 = 0; k0 < Ks; k0 += BKT) {
        #pragma unroll
        for (int i = 0; i < 4; i++) {
            int idx = tid + i*256, row = idx >> 3, c = (idx & 7)*4;
            float4 v = pa[i];
            __nv_bfloat16 h0 = __float2bfloat16(v.x), h1 = __float2bfloat16(v.y);
            __nv_bfloat16 h2 = __float2bfloat16(v.z), h3 = __float2bfloat16(v.w);
            __nv_bfloat16 l0 = __float2bfloat16(v.x - __bfloat162float(h0));
            __nv_bfloat16 l1 = __float2bfloat16(v.y - __bfloat162float(h1));
            __nv_bfloat16 l2 = __float2bfloat16(v.z - __bfloat162float(h2));
            __nv_bfloat16 l3 = __float2bfloat16(v.w - __bfloat162float(h3));
            __nv_bfloat162* dh = (__nv_bfloat162*)&Ah[row*LDA + c];
            __nv_bfloat162* dl = (__nv_bfloat162*)&Al[row*LDA + c];
            dh[0] = __halves2bfloat162(h0, h1); dh[1] = __halves2bfloat162(h2, h3);
            dl[0] = __halves2bfloat162(l0, l1); dl[1] = __halves2bfloat162(l2, l3);
        }
        #pragma unroll
        for (int i = 0; i < 2; i++) {
            int idx = tid + i*256, row = idx >> 3, c = (idx & 7)*4;
            float4 v = pw[i];
            __nv_bfloat16 h0 = __float2bfloat16(v.x), h1 = __float2bfloat16(v.y);
            __nv_bfloat16 h2 = __float2bfloat16(v.z), h3 = __float2bfloat16(v.w);
            __nv_bfloat16 l0 = __float2bfloat16(v.x - __bfloat162float(h0));
            __nv_bfloat16 l1 = __float2bfloat16(v.y - __bfloat162float(h1));
            __nv_bfloat16 l2 = __float2bfloat16(v.z - __bfloat162float(h2));
            __nv_bfloat16 l3 = __float2bfloat16(v.w - __bfloat162float(h3));
            __nv_bfloat162* dh = (__nv_bfloat162*)&Wh[row*LDA + c];
            __nv_bfloat162* dl = (__nv_bfloat162*)&Wl[row*LDA + c];
            dh[0] = __halves2bfloat162(h0, h1); dh[1] = __halves2bfloat162(h2, h3);
            dl[0] = __halves2bfloat162(l0, l1); dl[1] = __halves2bfloat162(l2, l3);
        }
        __syncthreads();

        if (k0 + BKT < Ks) {
            #pragma unroll
            for (int i = 0; i < 4; i++) {
                int idx = tid + i*256, row = idx >> 3, c = (idx & 7)*4;
                pa[i] = *(const float4*)(A + (size_t)(m0+row)*K + kbeg + k0 + BKT + c);
            }
            #pragma unroll
            for (int i = 0; i < 2; i++) {
                int idx = tid + i*256, row = idx >> 3, c = (idx & 7)*4;
                pw[i] = *(const float4*)(W + (size_t)(n0+row)*K + kbeg + k0 + BKT + c);
            }
        }

        #pragma unroll
        for (int ks = 0; ks < BKT; ks += 16) {
            wmma::fragment<wmma::matrix_a, 16, 16, 16, __nv_bfloat16, wmma::row_major> ah[2], al[2];
            #pragma unroll
            for (int i = 0; i < 2; i++) {
                wmma::load_matrix_sync(ah[i], Ah + (wm + i*16)*LDA + ks, LDA);
                wmma::load_matrix_sync(al[i], Al + (wm + i*16)*LDA + ks, LDA);
            }
            #pragma unroll
            for (int j = 0; j < 2; j++) {
                wmma::fragment<wmma::matrix_b, 16, 16, 16, __nv_bfloat16, wmma::col_major> bh, bl;
                wmma::load_matrix_sync(bh, Wh + (wn + j*16)*LDA + ks, LDA);
                wmma::load_matrix_sync(bl, Wl + (wn + j*16)*LDA + ks, LDA);
                #pragma unroll
                for (int i = 0; i < 2; i++) {
                    wmma::mma_sync(acc[i][j], ah[i], bh, acc[i][j]);
                    wmma::mma_sync(acc[i][j], ah[i], bl, acc[i][j]);
                    wmma::mma_sync(acc[i][j], al[i], bh, acc[i][j]);
                }
            }
        }
        __syncthreads();
    }

    if (S > 1) {
        float* Cp = C + (size_t)blockIdx.z*M*N;
        #pragma unroll
        for (int i = 0; i < 2; i++)
            #pragma unroll
            for (int j = 0; j < 2; j++)
                wmma::store_matrix_sync(Cp + (size_t)(m0+wm+i*16)*N + n0+wn+j*16,
                                        acc[i][j], N, wmma::mem_row_major);
        return;
    }

    #pragma unroll
    for (int i = 0; i < 2; i++)
        #pragma unroll
        for (int j = 0; j < 2; j++)
            wmma::store_matrix_sync(Ct + (wm+i*16)*LDC + wn+j*16,
                                    acc[i][j], LDC, wmma::mem_row_major);
    __syncthreads();

    int col = (tid & 15) * 4;
    int r0  = tid >> 4;
    float4 bv = make_float4(0.f, 0.f, 0.f, 0.f);
    if (bias) bv = *(const float4*)(bias + n0 + col);
    #pragma unroll
    for (int rr = 0; rr < 8; rr++) {
        int row = rr*16 + r0;
        float vr[4];
        *(float4*)vr = *(const float4*)&Ct[row*LDC + col];
        vr[0] += bv.x; vr[1] += bv.y; vr[2] += bv.z; vr[3] += bv.w;
        if (act == 1) {
            #pragma unroll
            for (int j = 0; j < 4; j++)
                vr[j] = 0.5f * vr[j] * (1.0f + erff(vr[j] * 0.7071067811865475f));
        }
        float* dst = C + (size_t)(m0+row)*N + n0 + col;
        if (res) {
            float4 r = *(const float4*)(res + (size_t)(m0+row)*N + n0 + col);
            vr[0]+=r.x; vr[1]+=r.y; vr[2]+=r.z; vr[3]+=r.w;
        }
        *(float4*)dst = *(float4*)vr;
    }
}

// ---------------- fused attention (QKV bias + scores + softmax + PV) ----------------
// grid: (Bc*Hc, 4), 256 threads; each warp handles 8 query rows.
__global__ __launch_bounds__(256) void attn_kernel(const float* __restrict__ qkv,
                                                   const float* __restrict__ qb,
                                                   const float* __restrict__ pr,
                                                   const float* __restrict__ ppw,
                                                   const float* __restrict__ ppb,
                                                   float* __restrict__ out) {
    int b = blockIdx.x >> 6;
    int h = blockIdx.x & 63;
    __shared__ float Ks[Nc*9];
    __shared__ float Vs[Nc*9];
    int tid = threadIdx.x;
    float4 bq0 = *(const float4*)(qb + h*HDc);
    float4 bq1 = *(const float4*)(qb + h*HDc + 4);
    float4 bk0 = *(const float4*)(qb + Dc + h*HDc);
    float4 bk1 = *(const float4*)(qb + Dc + h*HDc + 4);
    float4 bv0 = *(const float4*)(qb + 2*Dc + h*HDc);
    float4 bv1 = *(const float4*)(qb + 2*Dc + h*HDc + 4);
    {
        int n = tid;
        const float* kp = qkv + (((b*Nc + n)*3 + 1))*Dc + h*HDc;
        const float* vp = kp + Dc;
        float4 k0 = *(const float4*)kp,     k1 = *(const float4*)(kp+4);
        float4 v0 = *(const float4*)vp,     v1 = *(const float4*)(vp+4);
        float* kd = &Ks[n*9];
        kd[0]=k0.x+bk0.x; kd[1]=k0.y+bk0.y; kd[2]=k0.z+bk0.z; kd[3]=k0.w+bk0.w;
        kd[4]=k1.x+bk1.x; kd[5]=k1.y+bk1.y; kd[6]=k1.z+bk1.z; kd[7]=k1.w+bk1.w;
        float* vd = &Vs[n*9];
        vd[0]=v0.x+bv0.x; vd[1]=v0.y+bv0.y; vd[2]=v0.z+bv0.z; vd[3]=v0.w+bv0.w;
        vd[4]=v1.x+bv1.x; vd[5]=v1.y+bv1.y; vd[6]=v1.z+bv1.z; vd[7]=v1.w+bv1.w;
    }
    __syncthreads();
    const float scale = 0.3535533905932738f;
    float pw = ppw[h], pb = ppb[h];
    int warp = tid >> 5, lane = tid & 31;
    #pragma unroll
    for (int r = 0; r < 8; r++) {
        int i = blockIdx.y*64 + warp*8 + r;
        const float* qp = qkv + ((b*Nc + i)*3)*Dc + h*HDc;
        float4 q0 = *(const float4*)qp, q1 = *(const float4*)(qp+4);
        float qr[8];
        qr[0]=q0.x+bq0.x; qr[1]=q0.y+bq0.y; qr[2]=q0.z+bq0.z; qr[3]=q0.w+bq0.w;
        qr[4]=q1.x+bq1.x; qr[5]=q1.y+bq1.y; qr[6]=q1.z+bq1.z; qr[7]=q1.w+bq1.w;
        const float* prow = pr + (b*Nc + i)*Nc;
        float s[8];
        float mx = -1e30f;
        #pragma unroll
        for (int jj = 0; jj < 8; jj++) {
            int j = lane + 32*jj;
            const float* kk = &Ks[j*9];
            float d = qr[0]*kk[0] + qr[1]*kk[1] + qr[2]*kk[2] + qr[3]*kk[3]
                    + qr[4]*kk[4] + qr[5]*kk[5] + qr[6]*kk[6] + qr[7]*kk[7];
            s[jj] = d*scale + prow[j]*pw + pb;
            mx = fmaxf(mx, s[jj]);
        }
        #pragma unroll
        for (int off = 16; off; off >>= 1)
            mx = fmaxf(mx, __shfl_xor_sync(0xffffffff, mx, off));
        float sum = 0.f;
        #pragma unroll
        for (int jj = 0; jj < 8; jj++) { s[jj] = __expf(s[jj]-mx); sum += s[jj]; }
        #pragma unroll
        for (int off = 16; off; off >>= 1)
            sum += __shfl_xor_sync(0xffffffff, sum, off);
        float inv = 1.0f / sum;
        float acc[8] = {};
        #pragma unroll
        for (int jj = 0; jj < 8; jj++) {
            int j = lane + 32*jj;
            float p = s[jj]*inv;
            const float* vv = &Vs[j*9];
            #pragma unroll
            for (int d = 0; d < 8; d++) acc[d] += p*vv[d];
        }
        #pragma unroll
        for (int off = 16; off; off >>= 1) {
            #pragma unroll
            for (int d = 0; d < 8; d++)
                acc[d] += __shfl_xor_sync(0xffffffff, acc[d], off);
        }
        if (lane == 0) {
            float* op = out + (b*Nc + i)*Dc + h*HDc;
            #pragma unroll
            for (int d = 0; d < 8; d++) op[d] = acc[d];
        }
    }
}

// ---------------- SE(3) coordinate update ----------------
__global__ __launch_bounds__(128) void coords_kernel(const float* __restrict__ coords,
                                                     const float* __restrict__ pr,
                                                     const float* __restrict__ uw,
                                                     const float* __restrict__ ub,
                                                     const float* __restrict__ ww,
                                                     const float* __restrict__ wb,
                                                     float* __restrict__ out) {
    int gw = blockIdx.x * 4 + (threadIdx.x >> 5);
    int lane = threadIdx.x & 31;
    int b = gw >> 8, i = gw & 255;
    float u0 = uw[0], u1 = ub[0], w0 = ww[0], w1 = wb[0];
    const float* ci = coords + (b*Nc + i)*3;
    float cx = ci[0], cy = ci[1], cz = ci[2];
    float ax = 0.f, ay = 0.f, az = 0.f;
    const float* prow = pr + (b*Nc + i)*Nc;
    #pragma unroll
    for (int jj = 0; jj < 8; jj++) {
        int j = lane + 32*jj;
        const float* cj = coords + (b*Nc + j)*3;
        float c = (fmaxf(prow[j], 0.f)*u0 + u1)*w0 + w1;
        ax += (cx - cj[0])*c;
        ay += (cy - cj[1])*c;
        az += (cz - cj[2])*c;
    }
    #pragma unroll
    for (int off = 16; off; off >>= 1) {
        ax += __shfl_xor_sync(0xffffffff, ax, off);
        ay += __shfl_xor_sync(0xffffffff, ay, off);
        az += __shfl_xor_sync(0xffffffff, az, off);
    }
    if (lane == 0) {
        float invn = 1.0f / (256.0f + 1e-6f);
        float* op = out + (b*Nc + i)*3;
        op[0] = cx + ax*invn;
        op[1] = cy + ay*invn;
        op[2] = cz + az*invn;
    }
}

// ---------------- energy head ----------------
__global__ __launch_bounds__(128) void energy_kernel(const float* __restrict__ h,
                                                     const float* __restrict__ enw,
                                                     const float* __restrict__ enb,
                                                     float* __restrict__ out) {
    int b = blockIdx.x;
    int tid = threadIdx.x;
    const float* row = h + (b*Nc)*Dc;
    float s = 0.f;
    #pragma unroll
    for (int j = 0; j < 4; j++) {
        int d = tid + 128*j;
        s += row[d]*enw[d];
    }
    #pragma unroll
    for (int off = 16; off; off >>= 1)
        s += __shfl_xor_sync(0xffffffff, s, off);
    __shared__ float rs[4];
    int wid = tid >> 5, lane = tid & 31;
    if (lane == 0) rs[wid] = s;
    __syncthreads();
    if (tid == 0)
        out[Bc*Nc*3 + b] = rs[0]+rs[1]+rs[2]+rs[3] + enb[0];
}

// ---------------- host ----------------
extern "C" void kernel_launch(void* const* d_in, const int* in_sizes, int n_in,
                              void* d_out, int out_size) {
    bool has_mask = (n_in >= 31);
    auto IN = [&](int i) -> const void* {
        int k = i;
        if (!has_mask && i > 3) k = i - 1;
        return d_in[k];
    };
    const int*   atom_types = (const int*)  IN(0);
    const float* coords     = (const float*)IN(1);
    const int*   pair_types = (const int*)  IN(2);
    const float* atom_emb   = (const float*)IN(4);
    const float* gmu        = (const float*)IN(5);
    const float* gsigma     = (const float*)IN(6);
    const float* pair_a     = (const float*)IN(7);
    const float* pair_b     = (const float*)IN(8);
    const float* pl_w       = (const float*)IN(9);
    const float* pl_b       = (const float*)IN(10);
    const float* ln1_g      = (const float*)IN(11);
    const float* ln1_b      = (const float*)IN(12);
    const float* qkv_w      = (const float*)IN(13);
    const float* qkv_b      = (const float*)IN(14);
    const float* pp_w       = (const float*)IN(15);
    const float* pp_b       = (const float*)IN(16);
    const float* out_w      = (const float*)IN(17);
    const float* out_b      = (const float*)IN(18);
    const float* ln2_g      = (const float*)IN(19);
    const float* ln2_b      = (const float*)IN(20);
    const float* ffn_w1     = (const float*)IN(21);
    const float* ffn_b1     = (const float*)IN(22);
    const float* ffn_w2     = (const float*)IN(23);
    const float* ffn_b2     = (const float*)IN(24);
    const float* se3_uw     = (const float*)IN(25);
    const float* se3_ub     = (const float*)IN(26);
    const float* se3_ww     = (const float*)IN(27);
    const float* se3_wb     = (const float*)IN(28);
    const float* en_w       = (const float*)IN(29);
    const float* en_b       = (const float*)IN(30);
    float* out = (float*)d_out;

    float *hb, *xb, *qkvb, *attnb, *ffnb, *pairb, *splitb;
    cudaGetSymbolAddress((void**)&hb,     g_h);
    cudaGetSymbolAddress((void**)&xb,     g_x);
    cudaGetSymbolAddress((void**)&qkvb,   g_qkv);
    cudaGetSymbolAddress((void**)&attnb,  g_attn);
    cudaGetSymbolAddress((void**)&ffnb,   g_ffn);
    cudaGetSymbolAddress((void**)&pairb,  g_pair);
    cudaGetSymbolAddress((void**)&splitb, g_split);

    tab_kernel<<<(TABN + 256)/256, 256>>>(gmu, gsigma, pl_w, pl_b);
    emb_kernel<<<(Mc*Dc + 255)/256, 256>>>(atom_types, atom_emb, hb);
    pair_kernel<<<(Bc*Nc*Nc)/256, 256>>>(coords, pair_types, pair_a, pair_b, pairb);

    for (int l = 0; l < Lc; l++) {
        const float* l1g = ln1_g + l*Dc;
        const float* l1b = ln1_b + l*Dc;
        const float* qw  = qkv_w + (size_t)l*3*Dc*Dc;
        const float* qb  = qkv_b + l*3*Dc;
        const float* pwp = pp_w + l*Hc;
        const float* pbp = pp_b + l*Hc;
        const float* ow  = out_w + (size_t)l*Dc*Dc;
        const float* ob  = out_b + l*Dc;
        const float* l2g = ln2_g + l*Dc;
        const float* l2b = ln2_b + l*Dc;
        const float* w1  = ffn_w1 + (size_t)l*Fc*Dc;
        const float* b1  = ffn_b1 + l*Fc;
        const float* w2  = ffn_w2 + (size_t)l*Dc*Fc;
        const float* b2  = ffn_b2 + l*Dc;

        if (l == 0)
            ln_kernel<<<Mc, 128>>>(hb, l1g, l1b, xb);
        // QKV: raw output (bias folded into attention)
        gemm_bf16x3_kernel<<<dim3((3*Dc)/BN, Mc/BM, 1), 256>>>(
            xb, qw, nullptr, nullptr, qkvb, Mc, 3*Dc, Dc, 0);
        attn_kernel<<<dim3(Bc*Hc, 4), 256>>>(qkvb, qb, pairb, pwp, pbp, attnb);
        gemm_bf16x3_kernel<<<dim3(Dc/BN, Mc/BM, SPLITK), 256>>>(
            attnb, ow, nullptr, nullptr, splitb, Mc, Dc, Dc, 0);
        // h += out-proj + ob; x = LN2(h)
        reduce_ln_kernel<<<Mc, 128>>>(splitb, ob, hb, l2g, l2b, xb);
        gemm_bf16x3_kernel<<<dim3(Fc/BN, Mc/BM, 1), 256>>>(
            xb, w1, b1, nullptr, ffnb, Mc, Fc, Dc, 1);
        gemm_bf16x3_kernel<<<dim3(Dc/BN, Mc/BM, SPLITK), 256>>>(
            ffnb, w2, nullptr, nullptr, splitb, Mc, Dc, Fc, 0);
        if (l < Lc-1) {
            // h += ffn2 + b2; x = LN1(h) for next layer
            reduce_ln_kernel<<<Mc, 128>>>(splitb, b2, hb,
                                          ln1_g + (l+1)*Dc, ln1_b + (l+1)*Dc, xb);
        } else {
            reduce_splitk<<<(Mc*Dc/4 + 255)/256, 256>>>(splitb, b2, hb, Mc*Dc, Dc);
        }
    }

    coords_kernel<<<(Bc*Nc)/4, 128>>>(coords, pairb, se3_uw, se3_ub, se3_ww, se3_wb, out);
    energy_kernel<<<Bc, 128>>>(hb, en_w, en_b, out);
    (void)in_sizes; (void)out_size;
}

// round 10
// speedup vs baseline: 1.2321x; 1.0175x over previous
#include <cuda_runtime.h>
#include <cuda_bf16.h>
#include <mma.h>
#include <math.h>
#include <cstdint>
#include <stdint.h>

using namespace nvcuda;

// Problem constants
#define Lc 15
#define Dc 512
#define Hc 64
#define HDc 8
#define Fc 2048
#define Gc 128
#define Bc 4
#define Nc 256
#define Mc (Bc*Nc)   // 1024 rows
#define SPLITK 4
#define TABN 8192

// -------- scratch (device globals; no allocation allowed) --------
__device__ float g_h[Mc*Dc];
__device__ float g_x[Mc*Dc];
__device__ float g_qkv[Mc*3*Dc];
__device__ float g_attn[Mc*Dc];
__device__ float g_ffn[Mc*Fc];
__device__ float g_pair[Bc*Nc*Nc];
__device__ float g_split[SPLITK*Mc*Dc];
__device__ float g_tab[TABN+1];

// ---------------- gaussian table build ----------------
__global__ void tab_kernel(const float* __restrict__ mu,
                           const float* __restrict__ sigma,
                           const float* __restrict__ plw,
                           const float* __restrict__ plb) {
    int i = blockIdx.x*256 + threadIdx.x;
    if (i > TABN) return;
    float da = -8.0f + (float)i * (1.0f/512.0f);
    float s = 0.f;
    #pragma unroll 8
    for (int g = 0; g < Gc; g++) {
        float sg = sigma[g];
        float coef = plw[g] / (2.0f*sg*sg) / (sg * 2.5066282746310002f);
        float t = da - mu[g];
        s += __expf(-t*t) * coef;
    }
    g_tab[i] = s + plb[0];
}

// ---------------- pair representation via table lookup ----------------
__global__ void pair_kernel(const float* __restrict__ coords,
                            const int* __restrict__ ptypes,
                            const float* __restrict__ pa,
                            const float* __restrict__ pb,
                            float* __restrict__ pr) {
    int p = blockIdx.x * blockDim.x + threadIdx.x;
    int b = p >> 16;
    int rem = p & 65535;
    int i = rem >> 8, j = rem & 255;
    const float* ci = coords + (b*Nc + i)*3;
    const float* cj = coords + (b*Nc + j)*3;
    float dx = ci[0]-cj[0], dy = ci[1]-cj[1], dz = ci[2]-cj[2];
    float d2 = dx*dx + dy*dy + dz*dz;
    float dist = sqrtf(fmaxf(d2, 1e-12f));
    int pt = ptypes[p];
    float da = pa[pt]*dist + pb[pt];
    float t = (da + 8.0f) * 512.0f;
    t = fminf(fmaxf(t, 0.0f), (float)(TABN - 1));
    int idx = (int)t;
    float fr = t - (float)idx;
    float f0 = g_tab[idx], f1 = g_tab[idx+1];
    pr[p] = f0 + fr*(f1 - f0);
}

// ---------------- embedding ----------------
__global__ void emb_kernel(const int* __restrict__ atom_types,
                           const float* __restrict__ atom_emb,
                           float* __restrict__ h) {
    int idx = blockIdx.x * blockDim.x + threadIdx.x;
    if (idx >= Mc*Dc) return;
    int row = idx >> 9;
    int d   = idx & 511;
    h[idx] = atom_emb[atom_types[row]*Dc + d];
}

// ---------------- layernorm ----------------
__global__ __launch_bounds__(128) void ln_kernel(const float* __restrict__ in,
                                                 const float* __restrict__ g,
                                                 const float* __restrict__ bb,
                                                 float* __restrict__ out) {
    int row = blockIdx.x;
    int tid = threadIdx.x;
    const float* x = in + row*Dc;
    float v[4], s = 0.f, s2 = 0.f;
    #pragma unroll
    for (int j = 0; j < 4; j++) {
        v[j] = x[tid + 128*j];
        s += v[j]; s2 += v[j]*v[j];
    }
    #pragma unroll
    for (int off = 16; off; off >>= 1) {
        s  += __shfl_xor_sync(0xffffffff, s,  off);
        s2 += __shfl_xor_sync(0xffffffff, s2, off);
    }
    __shared__ float rs[4], rs2[4];
    int wid = tid >> 5, lane = tid & 31;
    if (lane == 0) { rs[wid] = s; rs2[wid] = s2; }
    __syncthreads();
    s  = rs[0]+rs[1]+rs[2]+rs[3];
    s2 = rs2[0]+rs2[1]+rs2[2]+rs2[3];
    float mean = s * (1.0f/Dc);
    float var  = s2 * (1.0f/Dc) - mean*mean;
    float rstd = rsqrtf(var + 1e-5f);
    #pragma unroll
    for (int j = 0; j < 4; j++) {
        int d = tid + 128*j;
        out[row*Dc + d] = (v[j]-mean)*rstd*g[d] + bb[d];
    }
}

// ---------------- fused split-K reduce + layernorm ----------------
__global__ __launch_bounds__(128) void reduce_ln_kernel(
    const float* __restrict__ P, const float* __restrict__ bias,
    float* __restrict__ h, const float* __restrict__ g,
    const float* __restrict__ bb, float* __restrict__ xout) {
    int row = blockIdx.x;
    int tid = threadIdx.x;
    const int MN = Mc*Dc;
    float v[4], s = 0.f, s2 = 0.f;
    #pragma unroll
    for (int j = 0; j < 4; j++) {
        int d = tid + 128*j;
        int idx = row*Dc + d;
        float val = h[idx] + bias[d]
                  + P[idx] + P[idx + MN] + P[idx + 2*MN] + P[idx + 3*MN];
        h[idx] = val;
        v[j] = val; s += val; s2 += val*val;
    }
    #pragma unroll
    for (int off = 16; off; off >>= 1) {
        s  += __shfl_xor_sync(0xffffffff, s,  off);
        s2 += __shfl_xor_sync(0xffffffff, s2, off);
    }
    __shared__ float rs[4], rs2[4];
    int wid = tid >> 5, lane = tid & 31;
    if (lane == 0) { rs[wid] = s; rs2[wid] = s2; }
    __syncthreads();
    s  = rs[0]+rs[1]+rs[2]+rs[3];
    s2 = rs2[0]+rs2[1]+rs2[2]+rs2[3];
    float mean = s * (1.0f/Dc);
    float var  = s2 * (1.0f/Dc) - mean*mean;
    float rstd = rsqrtf(var + 1e-5f);
    #pragma unroll
    for (int j = 0; j < 4; j++) {
        int d = tid + 128*j;
        xout[row*Dc + d] = (v[j]-mean)*rstd*g[d] + bb[d];
    }
}

// ---------------- plain split-K reduce (final layer) ----------------
__global__ __launch_bounds__(256) void reduce_splitk(const float* __restrict__ P,
                                                     const float* __restrict__ bias,
                                                     float* __restrict__ h,
                                                     int MN, int N) {
    int i4 = blockIdx.x*256 + threadIdx.x;
    if (i4 >= MN/4) return;
    int n = (i4*4) & (N-1);
    const float4* P4 = (const float4*)P;
    int stride4 = MN/4;
    float4 s0 = P4[i4];
    float4 s1 = P4[i4 + stride4];
    float4 s2 = P4[i4 + 2*stride4];
    float4 s3 = P4[i4 + 3*stride4];
    float4 b  = *(const float4*)(bias + n);
    float4 hv = ((float4*)h)[i4];
    hv.x += s0.x + s1.x + s2.x + s3.x + b.x;
    hv.y += s0.y + s1.y + s2.y + s3.y + b.y;
    hv.z += s0.z + s1.z + s2.z + s3.z + b.z;
    hv.w += s0.w + s1.w + s2.w + s3.w + b.w;
    ((float4*)h)[i4] = hv;
}

// ---------------- bf16x3 tensor-core GEMM, double-buffered, 1 sync/tile ----------------
#define BM 128
#define BN 64
#define BKT 32
#define LDA 40
#define LDC 68
#define SBUF 30720          // bytes per stage buffer (384 rows * 40 bf16 * 2B)
#define SMEM_DYN (2*SBUF)   // 61440
__global__ __launch_bounds__(256, 2) void gemm_bf16x3_kernel(
    const float* __restrict__ A, const float* __restrict__ W,
    const float* __restrict__ bias, const float* __restrict__ res,
    float* __restrict__ C, int M, int N, int K, int act)
{
    extern __shared__ __align__(16) char smem[];

    int tid = threadIdx.x;
    int m0 = blockIdx.y*BM, n0 = blockIdx.x*BN;
    int S = gridDim.z;
    int Ks = K / S;
    int kbeg = blockIdx.z * Ks;

    int wid = tid >> 5;
    int wm = (wid >> 1) * 32;
    int wn = (wid & 1) * 32;

    wmma::fragment<wmma::accumulator, 16, 16, 16, float> acc[2][2];
    #pragma unroll
    for (int i = 0; i < 2; i++)
        #pragma unroll
        for (int j = 0; j < 2; j++)
            wmma::fill_fragment(acc[i][j], 0.0f);

    // prefetch registers for tile 0
    float4 pa[4], pw[2];
    #pragma unroll
    for (int i = 0; i < 4; i++) {
        int idx = tid + i*256, row = idx >> 3, c = (idx & 7)*4;
        pa[i] = *(const float4*)(A + (size_t)(m0+row)*K + kbeg + c);
    }
    #pragma unroll
    for (int i = 0; i < 2; i++) {
        int idx = tid + i*256, row = idx >> 3, c = (idx & 7)*4;
        pw[i] = *(const float4*)(W + (size_t)(n0+row)*K + kbeg + c);
    }

    int nt = Ks / BKT;
    for (int t = 0; t < nt; t++) {
        char* buf = smem + (t & 1)*SBUF;
        __nv_bfloat16* Ah = (__nv_bfloat16*)buf;
        __nv_bfloat16* Al = Ah + BM*LDA;
        __nv_bfloat16* Wh = Al + BM*LDA;
        __nv_bfloat16* Wl = Wh + BN*LDA;

        // convert current regs -> buf[t&1]
        #pragma unroll
        for (int i = 0; i < 4; i++) {
            int idx = tid + i*256, row = idx >> 3, c = (idx & 7)*4;
            float4 v = pa[i];
            __nv_bfloat16 h0 = __float2bfloat16(v.x), h1 = __float2bfloat16(v.y);
            __nv_bfloat16 h2 = __float2bfloat16(v.z), h3 = __float2bfloat16(v.w);
            __nv_bfloat16 l0 = __float2bfloat16(v.x - __bfloat162float(h0));
            __nv_bfloat16 l1 = __float2bfloat16(v.y - __bfloat162float(h1));
            __nv_bfloat16 l2 = __float2bfloat16(v.z - __bfloat162float(h2));
            __nv_bfloat16 l3 = __float2bfloat16(v.w - __bfloat162float(h3));
            __nv_bfloat162* dh = (__nv_bfloat162*)&Ah[row*LDA + c];
            __nv_bfloat162* dl = (__nv_bfloat162*)&Al[row*LDA + c];
            dh[0] = __halves2bfloat162(h0, h1); dh[1] = __halves2bfloat162(h2, h3);
            dl[0] = __halves2bfloat162(l0, l1); dl[1] = __halves2bfloat162(l2, l3);
        }
        #pragma unroll
        for (int i = 0; i < 2; i++) {
            int idx = tid + i*256, row = idx >> 3, c = (idx & 7)*4;
            float4 v = pw[i];
            __nv_bfloat16 h0 = __float2bfloat16(v.x), h1 = __float2bfloat16(v.y);
            __nv_bfloat16 h2 = __float2bfloat16(v.z), h3 = __float2bfloat16(v.w);
            __nv_bfloat16 l0 = __float2bfloat16(v.x - __bfloat162float(h0));
            __nv_bfloat16 l1 = __float2bfloat16(v.y - __bfloat162float(h1));
            __nv_bfloat16 l2 = __float2bfloat16(v.z - __bfloat162float(h2));
            __nv_bfloat16 l3 = __float2bfloat16(v.w - __bfloat162float(h3));
            __nv_bfloat162* dh = (__nv_bfloat162*)&Wh[row*LDA + c];
            __nv_bfloat162* dl = (__nv_bfloat162*)&Wl[row*LDA + c];
            dh[0] = __halves2bfloat162(h0, h1); dh[1] = __halves2bfloat162(h2, h3);
            dl[0] = __halves2bfloat162(l0, l1); dl[1] = __halves2bfloat162(l2, l3);
        }

        // prefetch next tile into regs (latency hidden behind sync + mma)
        if (t + 1 < nt) {
            int k0 = (t+1)*BKT;
            #pragma unroll
            for (int i = 0; i < 4; i++) {
                int idx = tid + i*256, row = idx >> 3, c = (idx & 7)*4;
                pa[i] = *(const float4*)(A + (size_t)(m0+row)*K + kbeg + k0 + c);
            }
            #pragma unroll
            for (int i = 0; i < 2; i++) {
                int idx = tid + i*256, row = idx >> 3, c = (idx & 7)*4;
                pw[i] = *(const float4*)(W + (size_t)(n0+row)*K + kbeg + k0 + c);
            }
        }

        __syncthreads();   // the ONLY barrier per tile

        #pragma unroll
        for (int ks = 0; ks < BKT; ks += 16) {
            wmma::fragment<wmma::matrix_a, 16, 16, 16, __nv_bfloat16, wmma::row_major> ah[2], al[2];
            #pragma unroll
            for (int i = 0; i < 2; i++) {
                wmma::load_matrix_sync(ah[i], Ah + (wm + i*16)*LDA + ks, LDA);
                wmma::load_matrix_sync(al[i], Al + (wm + i*16)*LDA + ks, LDA);
            }
            #pragma unroll
            for (int j = 0; j < 2; j++) {
                wmma::fragment<wmma::matrix_b, 16, 16, 16, __nv_bfloat16, wmma::col_major> bh, bl;
                wmma::load_matrix_sync(bh, Wh + (wn + j*16)*LDA + ks, LDA);
                wmma::load_matrix_sync(bl, Wl + (wn + j*16)*LDA + ks, LDA);
                #pragma unroll
                for (int i = 0; i < 2; i++) {
                    wmma::mma_sync(acc[i][j], ah[i], bh, acc[i][j]);
                    wmma::mma_sync(acc[i][j], ah[i], bl, acc[i][j]);
                    wmma::mma_sync(acc[i][j], al[i], bh, acc[i][j]);
                }
            }
        }
        // no trailing sync: next iteration writes the OTHER buffer; the
        // pre-mma sync of iteration t+1 separates conv(t+2) from mma(t).
    }

    if (S > 1) {
        float* Cp = C + (size_t)blockIdx.z*M*N;
        #pragma unroll
        for (int i = 0; i < 2; i++)
            #pragma unroll
            for (int j = 0; j < 2; j++)
                wmma::store_matrix_sync(Cp + (size_t)(m0+wm+i*16)*N + n0+wn+j*16,
                                        acc[i][j], N, wmma::mem_row_major);
        return;
    }

    __syncthreads();   // before aliasing smem as the epilogue tile
    float* Ct = (float*)smem;
    #pragma unroll
    for (int i = 0; i < 2; i++)
        #pragma unroll
        for (int j = 0; j < 2; j++)
            wmma::store_matrix_sync(Ct + (wm+i*16)*LDC + wn+j*16,
                                    acc[i][j], LDC, wmma::mem_row_major);
    __syncthreads();

    int col = (tid & 15) * 4;
    int r0  = tid >> 4;
    float4 bv = make_float4(0.f, 0.f, 0.f, 0.f);
    if (bias) bv = *(const float4*)(bias + n0 + col);
    #pragma unroll
    for (int rr = 0; rr < 8; rr++) {
        int row = rr*16 + r0;
        float vr[4];
        *(float4*)vr = *(const float4*)&Ct[row*LDC + col];
        vr[0] += bv.x; vr[1] += bv.y; vr[2] += bv.z; vr[3] += bv.w;
        if (act == 1) {
            #pragma unroll
            for (int j = 0; j < 4; j++)
                vr[j] = 0.5f * vr[j] * (1.0f + erff(vr[j] * 0.7071067811865475f));
        }
        float* dst = C + (size_t)(m0+row)*N + n0 + col;
        if (res) {
            float4 r = *(const float4*)(res + (size_t)(m0+row)*N + n0 + col);
            vr[0]+=r.x; vr[1]+=r.y; vr[2]+=r.z; vr[3]+=r.w;
        }
        *(float4*)dst = *(float4*)vr;
    }
}

// ---------------- fused attention (QKV bias + scores + softmax + PV) ----------------
__global__ __launch_bounds__(256) void attn_kernel(const float* __restrict__ qkv,
                                                   const float* __restrict__ qb,
                                                   const float* __restrict__ pr,
                                                   const float* __restrict__ ppw,
                                                   const float* __restrict__ ppb,
                                                   float* __restrict__ out) {
    int b = blockIdx.x >> 6;
    int h = blockIdx.x & 63;
    __shared__ float Ks[Nc*9];
    __shared__ float Vs[Nc*9];
    int tid = threadIdx.x;
    float4 bq0 = *(const float4*)(qb + h*HDc);
    float4 bq1 = *(const float4*)(qb + h*HDc + 4);
    float4 bk0 = *(const float4*)(qb + Dc + h*HDc);
    float4 bk1 = *(const float4*)(qb + Dc + h*HDc + 4);
    float4 bv0 = *(const float4*)(qb + 2*Dc + h*HDc);
    float4 bv1 = *(const float4*)(qb + 2*Dc + h*HDc + 4);
    {
        int n = tid;
        const float* kp = qkv + (((b*Nc + n)*3 + 1))*Dc + h*HDc;
        const float* vp = kp + Dc;
        float4 k0 = *(const float4*)kp,     k1 = *(const float4*)(kp+4);
        float4 v0 = *(const float4*)vp,     v1 = *(const float4*)(vp+4);
        float* kd = &Ks[n*9];
        kd[0]=k0.x+bk0.x; kd[1]=k0.y+bk0.y; kd[2]=k0.z+bk0.z; kd[3]=k0.w+bk0.w;
        kd[4]=k1.x+bk1.x; kd[5]=k1.y+bk1.y; kd[6]=k1.z+bk1.z; kd[7]=k1.w+bk1.w;
        float* vd = &Vs[n*9];
        vd[0]=v0.x+bv0.x; vd[1]=v0.y+bv0.y; vd[2]=v0.z+bv0.z; vd[3]=v0.w+bv0.w;
        vd[4]=v1.x+bv1.x; vd[5]=v1.y+bv1.y; vd[6]=v1.z+bv1.z; vd[7]=v1.w+bv1.w;
    }
    __syncthreads();
    const float scale = 0.3535533905932738f;
    float pw = ppw[h], pb = ppb[h];
    int warp = tid >> 5, lane = tid & 31;
    #pragma unroll
    for (int r = 0; r < 8; r++) {
        int i = blockIdx.y*64 + warp*8 + r;
        const float* qp = qkv + ((b*Nc + i)*3)*Dc + h*HDc;
        float4 q0 = *(const float4*)qp, q1 = *(const float4*)(qp+4);
        float qr[8];
        qr[0]=q0.x+bq0.x; qr[1]=q0.y+bq0.y; qr[2]=q0.z+bq0.z; qr[3]=q0.w+bq0.w;
        qr[4]=q1.x+bq1.x; qr[5]=q1.y+bq1.y; qr[6]=q1.z+bq1.z; qr[7]=q1.w+bq1.w;
        const float* prow = pr + (b*Nc + i)*Nc;
        float s[8];
        float mx = -1e30f;
        #pragma unroll
        for (int jj = 0; jj < 8; jj++) {
            int j = lane + 32*jj;
            const float* kk = &Ks[j*9];
            float d = qr[0]*kk[0] + qr[1]*kk[1] + qr[2]*kk[2] + qr[3]*kk[3]
                    + qr[4]*kk[4] + qr[5]*kk[5] + qr[6]*kk[6] + qr[7]*kk[7];
            s[jj] = d*scale + prow[j]*pw + pb;
            mx = fmaxf(mx, s[jj]);
        }
        #pragma unroll
        for (int off = 16; off; off >>= 1)
            mx = fmaxf(mx, __shfl_xor_sync(0xffffffff, mx, off));
        float sum = 0.f;
        #pragma unroll
        for (int jj = 0; jj < 8; jj++) { s[jj] = __expf(s[jj]-mx); sum += s[jj]; }
        #pragma unroll
        for (int off = 16; off; off >>= 1)
            sum += __shfl_xor_sync(0xffffffff, sum, off);
        float inv = 1.0f / sum;
        float acc[8] = {};
        #pragma unroll
        for (int jj = 0; jj < 8; jj++) {
            int j = lane + 32*jj;
            float p = s[jj]*inv;
            const float* vv = &Vs[j*9];
            #pragma unroll
            for (int d = 0; d < 8; d++) acc[d] += p*vv[d];
        }
        #pragma unroll
        for (int off = 16; off; off >>= 1) {
            #pragma unroll
            for (int d = 0; d < 8; d++)
                acc[d] += __shfl_xor_sync(0xffffffff, acc[d], off);
        }
        if (lane == 0) {
            float* op = out + (b*Nc + i)*Dc + h*HDc;
            #pragma unroll
            for (int d = 0; d < 8; d++) op[d] = acc[d];
        }
    }
}

// ---------------- SE(3) coordinate update ----------------
__global__ __launch_bounds__(128) void coords_kernel(const float* __restrict__ coords,
                                                     const float* __restrict__ pr,
                                                     const float* __restrict__ uw,
                                                     const float* __restrict__ ub,
                                                     const float* __restrict__ ww,
                                                     const float* __restrict__ wb,
                                                     float* __restrict__ out) {
    int gw = blockIdx.x * 4 + (threadIdx.x >> 5);
    int lane = threadIdx.x & 31;
    int b = gw >> 8, i = gw & 255;
    float u0 = uw[0], u1 = ub[0], w0 = ww[0], w1 = wb[0];
    const float* ci = coords + (b*Nc + i)*3;
    float cx = ci[0], cy = ci[1], cz = ci[2];
    float ax = 0.f, ay = 0.f, az = 0.f;
    const float* prow = pr + (b*Nc + i)*Nc;
    #pragma unroll
    for (int jj = 0; jj < 8; jj++) {
        int j = lane + 32*jj;
        const float* cj = coords + (b*Nc + j)*3;
        float c = (fmaxf(prow[j], 0.f)*u0 + u1)*w0 + w1;
        ax += (cx - cj[0])*c;
        ay += (cy - cj[1])*c;
        az += (cz - cj[2])*c;
    }
    #pragma unroll
    for (int off = 16; off; off >>= 1) {
        ax += __shfl_xor_sync(0xffffffff, ax, off);
        ay += __shfl_xor_sync(0xffffffff, ay, off);
        az += __shfl_xor_sync(0xffffffff, az, off);
    }
    if (lane == 0) {
        float invn = 1.0f / (256.0f + 1e-6f);
        float* op = out + (b*Nc + i)*3;
        op[0] = cx + ax*invn;
        op[1] = cy + ay*invn;
        op[2] = cz + az*invn;
    }
}

// ---------------- energy head ----------------
__global__ __launch_bounds__(128) void energy_kernel(const float* __restrict__ h,
                                                     const float* __restrict__ enw,
                                                     const float* __restrict__ enb,
                                                     float* __restrict__ out) {
    int b = blockIdx.x;
    int tid = threadIdx.x;
    const float* row = h + (b*Nc)*Dc;
    float s = 0.f;
    #pragma unroll
    for (int j = 0; j < 4; j++) {
        int d = tid + 128*j;
        s += row[d]*enw[d];
    }
    #pragma unroll
    for (int off = 16; off; off >>= 1)
        s += __shfl_xor_sync(0xffffffff, s, off);
    __shared__ float rs[4];
    int wid = tid >> 5, lane = tid & 31;
    if (lane == 0) rs[wid] = s;
    __syncthreads();
    if (tid == 0)
        out[Bc*Nc*3 + b] = rs[0]+rs[1]+rs[2]+rs[3] + enb[0];
}

// ---------------- host ----------------
extern "C" void kernel_launch(void* const* d_in, const int* in_sizes, int n_in,
                              void* d_out, int out_size) {
    bool has_mask = (n_in >= 31);
    auto IN = [&](int i) -> const void* {
        int k = i;
        if (!has_mask && i > 3) k = i - 1;
        return d_in[k];
    };
    const int*   atom_types = (const int*)  IN(0);
    const float* coords     = (const float*)IN(1);
    const int*   pair_types = (const int*)  IN(2);
    const float* atom_emb   = (const float*)IN(4);
    const float* gmu        = (const float*)IN(5);
    const float* gsigma     = (const float*)IN(6);
    const float* pair_a     = (const float*)IN(7);
    const float* pair_b     = (const float*)IN(8);
    const float* pl_w       = (const float*)IN(9);
    const float* pl_b       = (const float*)IN(10);
    const float* ln1_g      = (const float*)IN(11);
    const float* ln1_b      = (const float*)IN(12);
    const float* qkv_w      = (const float*)IN(13);
    const float* qkv_b      = (const float*)IN(14);
    const float* pp_w       = (const float*)IN(15);
    const float* pp_b       = (const float*)IN(16);
    const float* out_w      = (const float*)IN(17);
    const float* out_b      = (const float*)IN(18);
    const float* ln2_g      = (const float*)IN(19);
    const float* ln2_b      = (const float*)IN(20);
    const float* ffn_w1     = (const float*)IN(21);
    const float* ffn_b1     = (const float*)IN(22);
    const float* ffn_w2     = (const float*)IN(23);
    const float* ffn_b2     = (const float*)IN(24);
    const float* se3_uw     = (const float*)IN(25);
    const float* se3_ub     = (const float*)IN(26);
    const float* se3_ww     = (const float*)IN(27);
    const float* se3_wb     = (const float*)IN(28);
    const float* en_w       = (const float*)IN(29);
    const float* en_b       = (const float*)IN(30);
    float* out = (float*)d_out;

    float *hb, *xb, *qkvb, *attnb, *ffnb, *pairb, *splitb;
    cudaGetSymbolAddress((void**)&hb,     g_h);
    cudaGetSymbolAddress((void**)&xb,     g_x);
    cudaGetSymbolAddress((void**)&qkvb,   g_qkv);
    cudaGetSymbolAddress((void**)&attnb,  g_attn);
    cudaGetSymbolAddress((void**)&ffnb,   g_ffn);
    cudaGetSymbolAddress((void**)&pairb,  g_pair);
    cudaGetSymbolAddress((void**)&splitb, g_split);

    cudaFuncSetAttribute(gemm_bf16x3_kernel,
                         cudaFuncAttributeMaxDynamicSharedMemorySize, SMEM_DYN);

    tab_kernel<<<(TABN + 256)/256, 256>>>(gmu, gsigma, pl_w, pl_b);
    emb_kernel<<<(Mc*Dc + 255)/256, 256>>>(atom_types, atom_emb, hb);
    pair_kernel<<<(Bc*Nc*Nc)/256, 256>>>(coords, pair_types, pair_a, pair_b, pairb);

    for (int l = 0; l < Lc; l++) {
        const float* l1g = ln1_g + l*Dc;
        const float* l1b = ln1_b + l*Dc;
        const float* qw  = qkv_w + (size_t)l*3*Dc*Dc;
        const float* qb  = qkv_b + l*3*Dc;
        const float* pwp = pp_w + l*Hc;
        const float* pbp = pp_b + l*Hc;
        const float* ow  = out_w + (size_t)l*Dc*Dc;
        const float* ob  = out_b + l*Dc;
        const float* l2g = ln2_g + l*Dc;
        const float* l2b = ln2_b + l*Dc;
        const float* w1  = ffn_w1 + (size_t)l*Fc*Dc;
        const float* b1  = ffn_b1 + l*Fc;
        const float* w2  = ffn_w2 + (size_t)l*Dc*Fc;
        const float* b2  = ffn_b2 + l*Dc;

        if (l == 0)
            ln_kernel<<<Mc, 128>>>(hb, l1g, l1b, xb);
        gemm_bf16x3_kernel<<<dim3((3*Dc)/BN, Mc/BM, 1), 256, SMEM_DYN>>>(
            xb, qw, nullptr, nullptr, qkvb, Mc, 3*Dc, Dc, 0);
        attn_kernel<<<dim3(Bc*Hc, 4), 256>>>(qkvb, qb, pairb, pwp, pbp, attnb);
        gemm_bf16x3_kernel<<<dim3(Dc/BN, Mc/BM, SPLITK), 256, SMEM_DYN>>>(
            attnb, ow, nullptr, nullptr, splitb, Mc, Dc, Dc, 0);
        reduce_ln_kernel<<<Mc, 128>>>(splitb, ob, hb, l2g, l2b, xb);
        gemm_bf16x3_kernel<<<dim3(Fc/BN, Mc/BM, 1), 256, SMEM_DYN>>>(
            xb, w1, b1, nullptr, ffnb, Mc, Fc, Dc, 1);
        gemm_bf16x3_kernel<<<dim3(Dc/BN, Mc/BM, SPLITK), 256, SMEM_DYN>>>(
            ffnb, w2, nullptr, nullptr, splitb, Mc, Dc, Fc, 0);
        if (l < Lc-1) {
            reduce_ln_kernel<<<Mc, 128>>>(splitb, b2, hb,
                                          ln1_g + (l+1)*Dc, ln1_b + (l+1)*Dc, xb);
        } else {
            reduce_splitk<<<(Mc*Dc/4 + 255)/256, 256>>>(splitb, b2, hb, Mc*Dc, Dc);
        }
    }

    coords_kernel<<<(Bc*Nc)/4, 128>>>(coords, pairb, se3_uw, se3_ub, se3_ww, se3_wb, out);
    energy_kernel<<<Bc, 128>>>(hb, en_w, en_b, out);
    (void)in_sizes; (void)out_size;
}